// round 4
// baseline (speedup 1.0000x reference)
#include <cuda_runtime.h>
#include <cuda_bf16.h>
#include <math.h>

// Problem constants
#define Bn   32
#define Sn   2048
#define Dn   1024           // ENC_D = DEC_D = ATTN_D = OUT_D
#define Mn   (Bn * Sn)      // 65536 rows of the big GEMM

// Score-GEMM tiling
#define BM 128
#define BN 64
#define BK 16
#define NTILES (Dn / BN)    // 16 column tiles

// Scratch (static device globals; no allocation allowed)
__device__ float g_decb[Bn * Dn];                 // dec_h + b_dec + b_enc  (combined bias)
__device__ float g_scores_part[NTILES * Mn];      // per-column-tile score partials (4 MB)
__device__ float g_ctx_part[16 * Bn * Dn];        // context partials over 16 S-chunks (2 MB)

// ---------------------------------------------------------------------------
// 1) decb[b,c] = b_dec[c] + b_enc[c] + sum_k dec_states[b,k] * W_dec[k,c]
// ---------------------------------------------------------------------------
__global__ void dech_kernel(const float* __restrict__ dec,
                            const float* __restrict__ Wdec,
                            const float* __restrict__ bdec,
                            const float* __restrict__ benc)
{
    int b = blockIdx.x;
    int tid = threadIdx.x;                 // 1024 threads, one output column each
    __shared__ float dsh[Dn];
    dsh[tid] = dec[b * Dn + tid];
    __syncthreads();
    float acc = bdec[tid] + benc[tid];
    #pragma unroll 4
    for (int k = 0; k < Dn; k++)
        acc = fmaf(dsh[k], Wdec[(size_t)k * Dn + tid], acc);
    g_decb[b * Dn + tid] = acc;
}

// ---------------------------------------------------------------------------
// 2) Fused score GEMM:
//    for each row r=(b,s), col tile tn:
//      scores_part[tn][r] = sum_{c in tile} tanh( (enc_states[r,:]@W_enc)[c]
//                                                 + decb[b,c] ) * w_attn[c]
//    BM=128 x BN=64 tile, BK=16, 256 threads, 8x4 microtile.
// ---------------------------------------------------------------------------
__global__ __launch_bounds__(256)
void score_gemm_kernel(const float* __restrict__ A,      // enc_states [Mn, Dn]
                       const float* __restrict__ Wenc,   // [Dn, Dn]
                       const float* __restrict__ wattn)  // [Dn]
{
    __shared__ float As[BM][BK];   // 8 KB
    __shared__ float Bs[BK][BN];   // 4 KB

    const int tid    = threadIdx.x;            // 0..255
    const int tile_m = blockIdx.x;             // 0..511
    const int tile_n = blockIdx.y;             // 0..15
    const int row0   = tile_m * BM;
    const int col0   = tile_n * BN;
    const int b      = row0 >> 11;             // row0 / 2048 (tile never spans batches)

    const int ty = tid >> 4;                   // 0..15 : row group of 8
    const int tx = tid & 15;                   // 0..15 : col group of 4

    float acc[8][4];
    #pragma unroll
    for (int i = 0; i < 8; i++)
        #pragma unroll
        for (int j = 0; j < 4; j++) acc[i][j] = 0.f;

    float4* As4 = reinterpret_cast<float4*>(&As[0][0]);
    float4* Bs4 = reinterpret_cast<float4*>(&Bs[0][0]);

    for (int k0 = 0; k0 < Dn; k0 += BK) {
        // Load A tile: 128x16 = 512 float4, 2 per thread
        #pragma unroll
        for (int i = 0; i < 2; i++) {
            int idx = tid + i * 256;           // float4 index
            int r   = idx >> 2;                // /4 (4 float4 per row)
            int c4  = idx & 3;
            As4[idx] = *reinterpret_cast<const float4*>(
                &A[(size_t)(row0 + r) * Dn + k0 + (c4 << 2)]);
        }
        // Load B tile: 16x64 = 256 float4, 1 per thread
        {
            int idx = tid;
            int k   = idx >> 4;                // /16 (16 float4 per row)
            int n4  = idx & 15;
            Bs4[idx] = *reinterpret_cast<const float4*>(
                &Wenc[(size_t)(k0 + k) * Dn + col0 + (n4 << 2)]);
        }
        __syncthreads();

        #pragma unroll
        for (int kk = 0; kk < BK; kk++) {
            float a[8];
            #pragma unroll
            for (int i = 0; i < 8; i++) a[i] = As[ty * 8 + i][kk];
            float4 bb = *reinterpret_cast<float4*>(&Bs[kk][tx * 4]);
            #pragma unroll
            for (int i = 0; i < 8; i++) {
                acc[i][0] = fmaf(a[i], bb.x, acc[i][0]);
                acc[i][1] = fmaf(a[i], bb.y, acc[i][1]);
                acc[i][2] = fmaf(a[i], bb.z, acc[i][2]);
                acc[i][3] = fmaf(a[i], bb.w, acc[i][3]);
            }
        }
        __syncthreads();
    }

    // Epilogue: tanh(acc + decb) * w_attn, reduce the 64-col tile per row.
    float wv[4], db[4];
    #pragma unroll
    for (int j = 0; j < 4; j++) {
        int c = col0 + tx * 4 + j;
        wv[j] = wattn[c];
        db[j] = g_decb[b * Dn + c];
    }
    float rowsum[8];
    #pragma unroll
    for (int i = 0; i < 8; i++) {
        float s = 0.f;
        #pragma unroll
        for (int j = 0; j < 4; j++)
            s += tanhf(acc[i][j] + db[j]) * wv[j];
        // reduce across the 16 tx lanes (lane = (ty&1)*16 + tx; xor<16 stays in group)
        s += __shfl_xor_sync(0xffffffffu, s, 8);
        s += __shfl_xor_sync(0xffffffffu, s, 4);
        s += __shfl_xor_sync(0xffffffffu, s, 2);
        s += __shfl_xor_sync(0xffffffffu, s, 1);
        rowsum[i] = s;
    }
    if (tx == 0) {
        #pragma unroll
        for (int i = 0; i < 8; i++)
            g_scores_part[tile_n * Mn + row0 + ty * 8 + i] = rowsum[i];
    }
}

// ---------------------------------------------------------------------------
// 3) Masked softmax per batch row; writes attn into d_out[32768 + b*2048 + s]
// ---------------------------------------------------------------------------
__global__ void softmax_kernel(const int* __restrict__ enc_len,
                               float* __restrict__ attn_out)   // d_out + Bn*Dn
{
    const int b   = blockIdx.x;
    const int tid = threadIdx.x;              // 256
    __shared__ float red[256];
    __shared__ float sc[Sn];

    const int len = enc_len[b];

    float lmax = -INFINITY;
    for (int s = tid; s < Sn; s += 256) {
        float v = 0.f;
        #pragma unroll
        for (int ct = 0; ct < NTILES; ct++)
            v += g_scores_part[ct * Mn + b * Sn + s];
        sc[s] = v;
        if (s < len) lmax = fmaxf(lmax, v);
    }
    red[tid] = lmax;
    __syncthreads();
    for (int off = 128; off > 0; off >>= 1) {
        if (tid < off) red[tid] = fmaxf(red[tid], red[tid + off]);
        __syncthreads();
    }
    const float m = red[0];
    __syncthreads();

    float lsum = 0.f;
    for (int s = tid; s < Sn; s += 256) {
        float e = (s < len) ? expf(sc[s] - m) : 0.f;
        sc[s] = e;
        lsum += e;
    }
    red[tid] = lsum;
    __syncthreads();
    for (int off = 128; off > 0; off >>= 1) {
        if (tid < off) red[tid] += red[tid + off];
        __syncthreads();
    }
    const float inv = 1.f / red[0];
    __syncthreads();

    for (int s = tid; s < Sn; s += 256)
        attn_out[b * Sn + s] = sc[s] * inv;
}

// ---------------------------------------------------------------------------
// 4) Context partials: ctx_part[ch][b][d] = sum_{s in chunk} attn[b,s]*enc[b,s,d]
// ---------------------------------------------------------------------------
__global__ void context_kernel(const float* __restrict__ enc,
                               const float* __restrict__ attn)   // from d_out
{
    const int ch  = blockIdx.x;     // 16 S-chunks of 128
    const int b   = blockIdx.y;     // 32
    const int tid = threadIdx.x;    // 256 threads, 4 dims each
    const int d   = tid * 4;
    __shared__ float wsh[128];
    if (tid < 128) wsh[tid] = attn[b * Sn + ch * 128 + tid];
    __syncthreads();

    float4 acc = make_float4(0.f, 0.f, 0.f, 0.f);
    const int s0 = ch * 128;
    for (int i = 0; i < 128; i++) {
        float w = wsh[i];
        float4 e = *reinterpret_cast<const float4*>(
            &enc[((size_t)b * Sn + s0 + i) * Dn + d]);
        acc.x = fmaf(w, e.x, acc.x);
        acc.y = fmaf(w, e.y, acc.y);
        acc.z = fmaf(w, e.z, acc.z);
        acc.w = fmaf(w, e.w, acc.w);
    }
    *reinterpret_cast<float4*>(&g_ctx_part[((size_t)ch * Bn + b) * Dn + d]) = acc;
}

// ---------------------------------------------------------------------------
// 5) Output GEMM: out[b,:] = (sum_ch ctx_part[ch][b]) @ W_out + b_out
// ---------------------------------------------------------------------------
__global__ void out_kernel(const float* __restrict__ Wout,
                           const float* __restrict__ bout,
                           float* __restrict__ out)              // d_out
{
    const int b   = blockIdx.x;
    const int tid = threadIdx.x;   // 1024
    __shared__ float ctx[Dn];
    float v = 0.f;
    #pragma unroll
    for (int ch = 0; ch < 16; ch++)
        v += g_ctx_part[((size_t)ch * Bn + b) * Dn + tid];
    ctx[tid] = v;
    __syncthreads();
    float acc = bout[tid];
    #pragma unroll 4
    for (int k = 0; k < Dn; k++)
        acc = fmaf(ctx[k], Wout[(size_t)k * Dn + tid], acc);
    out[b * Dn + tid] = acc;
}

// ---------------------------------------------------------------------------
// Launch. Inputs (metadata order):
// 0 enc_states [B,S,ENC_D] f32   1 dec_states [B,DEC_D] f32
// 2 W_enc [1024,1024]            3 b_enc [1024]
// 4 W_dec [1024,1024]            5 b_dec [1024]
// 6 w_attn [1024]                7 W_out [1024,1024]
// 8 b_out [1024]                 9 enc_len [B] i32
// Output: context [32,1024] then attn [32,2048], fp32, flat.
// ---------------------------------------------------------------------------
extern "C" void kernel_launch(void* const* d_in, const int* in_sizes, int n_in,
                              void* d_out, int out_size)
{
    const float* enc   = (const float*)d_in[0];
    const float* dec   = (const float*)d_in[1];
    const float* Wenc  = (const float*)d_in[2];
    const float* benc  = (const float*)d_in[3];
    const float* Wdec  = (const float*)d_in[4];
    const float* bdec  = (const float*)d_in[5];
    const float* wattn = (const float*)d_in[6];
    const float* Wout  = (const float*)d_in[7];
    const float* bout  = (const float*)d_in[8];
    const int*   elen  = (const int*)d_in[9];

    float* out      = (float*)d_out;            // context [32*1024]
    float* attn_out = out + Bn * Dn;            // attn    [32*2048]

    dech_kernel<<<Bn, Dn>>>(dec, Wdec, bdec, benc);
    score_gemm_kernel<<<dim3(Mn / BM, NTILES), 256>>>(enc, Wenc, wattn);
    softmax_kernel<<<Bn, 256>>>(elen, attn_out);
    context_kernel<<<dim3(16, Bn), 256>>>(enc, attn_out);
    out_kernel<<<Bn, Dn>>>(Wout, bout, out);
}

// round 7
// speedup vs baseline: 4.1274x; 4.1274x over previous
#include <cuda_runtime.h>
#include <cuda_bf16.h>
#include <cstdint>
#include <math.h>

// Problem constants
#define Bn   32
#define Sn   2048
#define Dn   1024
#define Mn   (Bn * Sn)

// Score-GEMM tiling (mma.sync HMMA path — tcgen05 PTX is rejected by the
// harness's compute_103 PTX stage, so we use the arch-portable tensor path)
#define BM 128
#define BN 64
#define BK 32
#define NTILES (Dn / BN)    // 16 column tiles
#define NCHUNK (Dn / BK)    // 32 K chunks

// ---------------------------------------------------------------------------
// Scratch (static device globals; no allocation allowed)
// ---------------------------------------------------------------------------
__device__ float g_decb[Bn * Dn];                    // dec_h + b_dec + b_enc
__device__ float g_scores_part[NTILES * Mn];         // per-col-tile score partials
__device__ float g_ctx_part[16 * Bn * Dn];           // context partials
__device__ __nv_bfloat16 g_encb[(size_t)Mn * Dn];    // enc_states bf16 (128 MB)
__device__ __nv_bfloat16 g_WTh[Dn * Dn];             // W_enc^T hi (K-major: [n][k])
__device__ __nv_bfloat16 g_WTl[Dn * Dn];             // W_enc^T lo

// ---------------------------------------------------------------------------
// PTX helpers (sm_80-compatible only: cp.async, ldmatrix, mma.sync)
// ---------------------------------------------------------------------------
__device__ __forceinline__ uint32_t smem_u32(const void* p) {
    uint32_t a;
    asm("{ .reg .u64 t; cvta.to.shared.u64 t, %1; cvt.u32.u64 %0, t; }" : "=r"(a) : "l"(p));
    return a;
}
__device__ __forceinline__ void cp_async16(uint32_t dst, const void* src) {
    asm volatile("cp.async.cg.shared.global [%0], [%1], 16;" :: "r"(dst), "l"(src));
}
__device__ __forceinline__ void cp_commit() {
    asm volatile("cp.async.commit_group;" ::: "memory");
}
template <int N>
__device__ __forceinline__ void cp_wait() {
    asm volatile("cp.async.wait_group %0;" :: "n"(N) : "memory");
}
__device__ __forceinline__ void ldsm4(uint32_t* r, uint32_t addr) {
    asm volatile("ldmatrix.sync.aligned.m8n8.x4.shared.b16 {%0,%1,%2,%3}, [%4];"
                 : "=r"(r[0]), "=r"(r[1]), "=r"(r[2]), "=r"(r[3]) : "r"(addr));
}
__device__ __forceinline__ void mma16816(float* c, const uint32_t* a,
                                         uint32_t b0, uint32_t b1) {
    asm volatile("mma.sync.aligned.m16n8k16.row.col.f32.bf16.bf16.f32 "
                 "{%0,%1,%2,%3}, {%4,%5,%6,%7}, {%8,%9}, {%0,%1,%2,%3};"
                 : "+f"(c[0]), "+f"(c[1]), "+f"(c[2]), "+f"(c[3])
                 : "r"(a[0]), "r"(a[1]), "r"(a[2]), "r"(a[3]), "r"(b0), "r"(b1));
}

// ---------------------------------------------------------------------------
// Pre-pass A: enc_states fp32 -> bf16 (RN)
// ---------------------------------------------------------------------------
__global__ void convert_enc(const float* __restrict__ enc) {
    size_t i = (size_t)blockIdx.x * blockDim.x + threadIdx.x;  // one float4 each
    float4 v = reinterpret_cast<const float4*>(enc)[i];
    __nv_bfloat162 p0 = __floats2bfloat162_rn(v.x, v.y);
    __nv_bfloat162 p1 = __floats2bfloat162_rn(v.z, v.w);
    uint2 u;
    u.x = *reinterpret_cast<uint32_t*>(&p0);
    u.y = *reinterpret_cast<uint32_t*>(&p1);
    reinterpret_cast<uint2*>(g_encb)[i] = u;
}

// ---------------------------------------------------------------------------
// Pre-pass B: W_enc [K,N] fp32 -> transposed K-major bf16 hi/lo pair
// ---------------------------------------------------------------------------
__global__ void convert_W(const float* __restrict__ W) {
    int n = blockIdx.x;
    int k = threadIdx.x;
    float w = W[(size_t)k * Dn + n];
    __nv_bfloat16 hi = __float2bfloat16_rn(w);
    __nv_bfloat16 lo = __float2bfloat16_rn(w - __bfloat162float(hi));
    g_WTh[(size_t)n * Dn + k] = hi;
    g_WTl[(size_t)n * Dn + k] = lo;
}

// ---------------------------------------------------------------------------
// decb[b,c] = b_dec[c] + b_enc[c] + dec_states[b,:] @ W_dec[:,c]
// ---------------------------------------------------------------------------
__global__ void dech_kernel(const float* __restrict__ dec,
                            const float* __restrict__ Wdec,
                            const float* __restrict__ bdec,
                            const float* __restrict__ benc) {
    int b = blockIdx.x;
    int tid = threadIdx.x;
    __shared__ float dsh[Dn];
    dsh[tid] = dec[b * Dn + tid];
    __syncthreads();
    float acc = bdec[tid] + benc[tid];
    #pragma unroll 4
    for (int k = 0; k < Dn; k++)
        acc = fmaf(dsh[k], Wdec[(size_t)k * Dn + tid], acc);
    g_decb[b * Dn + tid] = acc;
}

// ---------------------------------------------------------------------------
// HMMA fused score GEMM.
//  D[128,64] = A_bf16[128,K] @ (Bhi+Blo)[64,K]^T  (accumulated in fp32)
//  epilogue: rowsum of tanh(D + decb) * w_attn -> g_scores_part[tile_n][row]
//  8 warps in 4(M) x 2(N); each warp owns a 32x32 sub-tile.
//  SMEM rows padded to 40 bf16 (80 B): ldmatrix 8-lane address groups land on
//  disjoint bank quads (stride = 20 banks) -> conflict-free.
// ---------------------------------------------------------------------------
struct Stage {
    __nv_bfloat16 A[BM][40];
    __nv_bfloat16 Bh[BN][40];
    __nv_bfloat16 Bl[BN][40];
};

__global__ __launch_bounds__(256)
void score_gemm_hmma(const float* __restrict__ wattn) {
    __shared__ __align__(16) Stage stg[2];
    __shared__ float s_db[BN], s_w[BN];
    __shared__ float rowsum[2][BM];

    const int tid  = threadIdx.x;
    const int wid  = tid >> 5;
    const int lane = tid & 31;
    const int wm   = wid >> 1;     // 0..3 : 32-row group
    const int wn   = wid & 1;      // 0..1 : 32-col group
    const int n0   = blockIdx.x * BN;   // x = col tile -> 16 CTAs share A in L2
    const int m0   = blockIdx.y * BM;
    const int b    = m0 >> 11;

    if (tid < BN) {
        s_db[tid] = g_decb[b * Dn + n0 + tid];
        s_w[tid]  = wattn[n0 + tid];
    }

    float acc[2][4][4];
    #pragma unroll
    for (int i = 0; i < 2; i++)
        #pragma unroll
        for (int j = 0; j < 4; j++)
            #pragma unroll
            for (int q = 0; q < 4; q++) acc[i][j][q] = 0.f;

    const __nv_bfloat16* __restrict__ Ab = g_encb + (size_t)m0 * Dn;

    auto load_chunk = [&](int c) {
        const int st = c & 1;
        const int k0 = c * BK;
        #pragma unroll
        for (int i = 0; i < 2; i++) {                 // A: 128 rows x 4 x 16B
            int seg = tid + i * 256;
            int r = seg >> 2, s = seg & 3;
            cp_async16(smem_u32(&stg[st].A[r][s * 8]),
                       Ab + (size_t)r * Dn + k0 + s * 8);
        }
        {                                             // Bh/Bl: 64 rows x 4 x 16B
            int r = tid >> 2, s = tid & 3;
            const size_t g = (size_t)(n0 + r) * Dn + k0 + s * 8;
            cp_async16(smem_u32(&stg[st].Bh[r][s * 8]), g_WTh + g);
            cp_async16(smem_u32(&stg[st].Bl[r][s * 8]), g_WTl + g);
        }
        cp_commit();
    };

    load_chunk(0);
    load_chunk(1);

    for (int c = 0; c < NCHUNK; c++) {
        if (c == NCHUNK - 1) cp_wait<0>(); else cp_wait<1>();
        __syncthreads();
        const Stage& S = stg[c & 1];

        #pragma unroll
        for (int kk = 0; kk < 2; kk++) {              // two k16 steps per chunk
            const int kb = kk * 16;
            // A frags: 2 x ldmatrix.x4 (rows wm*32 .. +31)
            uint32_t a[2][4];
            #pragma unroll
            for (int mi = 0; mi < 2; mi++) {
                int row = wm * 32 + mi * 16 + (lane & 15);
                int col = kb + (lane >> 4) * 8;
                ldsm4(a[mi], smem_u32(&S.A[row][col]));
            }
            // B frags (col-major [n][k]): per 16-col pair one x4 for hi and lo
            uint32_t bh[2][4], bl[2][4];
            const int quad = lane >> 3;
            #pragma unroll
            for (int p = 0; p < 2; p++) {
                int nrow = wn * 32 + p * 16 + ((quad & 2) ? 8 : 0) + (lane & 7);
                int kcol = kb + ((quad & 1) ? 8 : 0);
                ldsm4(bh[p], smem_u32(&S.Bh[nrow][kcol]));
                ldsm4(bl[p], smem_u32(&S.Bl[nrow][kcol]));
            }
            #pragma unroll
            for (int mi = 0; mi < 2; mi++)
                #pragma unroll
                for (int p = 0; p < 2; p++)
                    #pragma unroll
                    for (int sub = 0; sub < 2; sub++) {
                        int nf = p * 2 + sub;
                        mma16816(acc[mi][nf], a[mi], bh[p][sub * 2], bh[p][sub * 2 + 1]);
                        mma16816(acc[mi][nf], a[mi], bl[p][sub * 2], bl[p][sub * 2 + 1]);
                    }
        }
        __syncthreads();
        if (c + 2 < NCHUNK) load_chunk(c + 2);
    }

    // Epilogue: rowsum of tanh(acc + decb) * w_attn
    // c-frag layout: c0,c1 -> row lane/4,  cols 2*(lane%4)+{0,1};  c2,c3 -> row +8
    #pragma unroll
    for (int mi = 0; mi < 2; mi++) {
        float sl = 0.f, sh = 0.f;
        #pragma unroll
        for (int nf = 0; nf < 4; nf++) {
            int cb = wn * 32 + nf * 8 + (lane & 3) * 2;
            sl += tanhf(acc[mi][nf][0] + s_db[cb])     * s_w[cb]
                + tanhf(acc[mi][nf][1] + s_db[cb + 1]) * s_w[cb + 1];
            sh += tanhf(acc[mi][nf][2] + s_db[cb])     * s_w[cb]
                + tanhf(acc[mi][nf][3] + s_db[cb + 1]) * s_w[cb + 1];
        }
        sl += __shfl_xor_sync(0xffffffffu, sl, 1);
        sl += __shfl_xor_sync(0xffffffffu, sl, 2);
        sh += __shfl_xor_sync(0xffffffffu, sh, 1);
        sh += __shfl_xor_sync(0xffffffffu, sh, 2);
        if ((lane & 3) == 0) {
            int r = wm * 32 + mi * 16 + (lane >> 2);
            rowsum[wn][r]     = sl;
            rowsum[wn][r + 8] = sh;
        }
    }
    __syncthreads();
    if (tid < BM)
        g_scores_part[blockIdx.x * Mn + m0 + tid] = rowsum[0][tid] + rowsum[1][tid];
}

// ---------------------------------------------------------------------------
// Masked softmax per batch row; writes attn into d_out[32768 + b*2048 + s]
// ---------------------------------------------------------------------------
__global__ void softmax_kernel(const int* __restrict__ enc_len,
                               float* __restrict__ attn_out) {
    const int b = blockIdx.x;
    const int tid = threadIdx.x;
    __shared__ float red[256];
    __shared__ float sc[Sn];

    const int len = enc_len[b];

    float lmax = -INFINITY;
    for (int s = tid; s < Sn; s += 256) {
        float v = 0.f;
        #pragma unroll
        for (int ct = 0; ct < NTILES; ct++)
            v += g_scores_part[ct * Mn + b * Sn + s];
        sc[s] = v;
        if (s < len) lmax = fmaxf(lmax, v);
    }
    red[tid] = lmax;
    __syncthreads();
    for (int off = 128; off > 0; off >>= 1) {
        if (tid < off) red[tid] = fmaxf(red[tid], red[tid + off]);
        __syncthreads();
    }
    const float m = red[0];
    __syncthreads();

    float lsum = 0.f;
    for (int s = tid; s < Sn; s += 256) {
        float e = (s < len) ? expf(sc[s] - m) : 0.f;
        sc[s] = e;
        lsum += e;
    }
    red[tid] = lsum;
    __syncthreads();
    for (int off = 128; off > 0; off >>= 1) {
        if (tid < off) red[tid] += red[tid + off];
        __syncthreads();
    }
    const float inv = 1.f / red[0];
    __syncthreads();

    for (int s = tid; s < Sn; s += 256)
        attn_out[b * Sn + s] = sc[s] * inv;
}

// ---------------------------------------------------------------------------
// Context partials (fp32 enc_states for accuracy)
// ---------------------------------------------------------------------------
__global__ void context_kernel(const float* __restrict__ enc,
                               const float* __restrict__ attn) {
    const int ch = blockIdx.x;
    const int b = blockIdx.y;
    const int tid = threadIdx.x;
    const int d = tid * 4;
    __shared__ float wsh[128];
    if (tid < 128) wsh[tid] = attn[b * Sn + ch * 128 + tid];
    __syncthreads();

    float4 acc = make_float4(0.f, 0.f, 0.f, 0.f);
    const int s0 = ch * 128;
    for (int i = 0; i < 128; i++) {
        float w = wsh[i];
        float4 e = *reinterpret_cast<const float4*>(
            &enc[((size_t)b * Sn + s0 + i) * Dn + d]);
        acc.x = fmaf(w, e.x, acc.x);
        acc.y = fmaf(w, e.y, acc.y);
        acc.z = fmaf(w, e.z, acc.z);
        acc.w = fmaf(w, e.w, acc.w);
    }
    *reinterpret_cast<float4*>(&g_ctx_part[((size_t)ch * Bn + b) * Dn + d]) = acc;
}

// ---------------------------------------------------------------------------
// Output GEMM
// ---------------------------------------------------------------------------
__global__ void out_kernel(const float* __restrict__ Wout,
                           const float* __restrict__ bout,
                           float* __restrict__ out) {
    const int b = blockIdx.x;
    const int tid = threadIdx.x;
    __shared__ float ctx[Dn];
    float v = 0.f;
    #pragma unroll
    for (int ch = 0; ch < 16; ch++)
        v += g_ctx_part[((size_t)ch * Bn + b) * Dn + tid];
    ctx[tid] = v;
    __syncthreads();
    float acc = bout[tid];
    #pragma unroll 4
    for (int k = 0; k < Dn; k++)
        acc = fmaf(ctx[k], Wout[(size_t)k * Dn + tid], acc);
    out[b * Dn + tid] = acc;
}

// ---------------------------------------------------------------------------
// Launch
// ---------------------------------------------------------------------------
extern "C" void kernel_launch(void* const* d_in, const int* in_sizes, int n_in,
                              void* d_out, int out_size) {
    const float* enc   = (const float*)d_in[0];
    const float* dec   = (const float*)d_in[1];
    const float* Wenc  = (const float*)d_in[2];
    const float* benc  = (const float*)d_in[3];
    const float* Wdec  = (const float*)d_in[4];
    const float* bdec  = (const float*)d_in[5];
    const float* wattn = (const float*)d_in[6];
    const float* Wout  = (const float*)d_in[7];
    const float* bout  = (const float*)d_in[8];
    const int*   elen  = (const int*)d_in[9];

    float* out      = (float*)d_out;       // context [32*1024]
    float* attn_out = out + Bn * Dn;       // attn    [32*2048]

    convert_enc<<<(Mn * (Dn / 4)) / 256, 256>>>(enc);
    convert_W<<<Dn, Dn>>>(Wenc);
    dech_kernel<<<Bn, Dn>>>(dec, Wdec, bdec, benc);
    score_gemm_hmma<<<dim3(NTILES, Mn / BM), 256>>>(wattn);
    softmax_kernel<<<Bn, 256>>>(elen, attn_out);
    context_kernel<<<dim3(16, Bn), 256>>>(enc, attn_out);
    out_kernel<<<Bn, Dn>>>(Wout, bout, out);
}

// round 8
// speedup vs baseline: 4.3689x; 1.0585x over previous
#include <cuda_runtime.h>
#include <cuda_bf16.h>
#include <cstdint>
#include <math.h>

// Problem constants
#define Bn   32
#define Sn   2048
#define Dn   1024
#define Mn   (Bn * Sn)

// Score-GEMM tiling (mma.sync HMMA path — tcgen05 PTX is rejected by the
// harness's compute_103 PTX stage, so we use the arch-portable tensor path)
#define BM 128
#define BN 64
#define BK 32
#define NTILES (Dn / BN)    // 16 column tiles
#define NCHUNK (Dn / BK)    // 32 K chunks

// ---------------------------------------------------------------------------
// Scratch (static device globals; no allocation allowed)
// ---------------------------------------------------------------------------
__device__ float g_decb[Bn * Dn];                    // dec_h + b_dec + b_enc
__device__ float g_scores_part[NTILES * Mn];         // per-col-tile score partials
__device__ float g_ctx_part[16 * Bn * Dn];           // context partials
__device__ __nv_bfloat16 g_encb[(size_t)Mn * Dn];    // enc_states bf16 (128 MB)
__device__ __nv_bfloat16 g_WTh[Dn * Dn];             // W_enc^T hi (K-major: [n][k])
__device__ __nv_bfloat16 g_WTl[Dn * Dn];             // W_enc^T lo

// ---------------------------------------------------------------------------
// PTX helpers (sm_80-compatible only: cp.async, ldmatrix, mma.sync)
// ---------------------------------------------------------------------------
__device__ __forceinline__ uint32_t smem_u32(const void* p) {
    uint32_t a;
    asm("{ .reg .u64 t; cvta.to.shared.u64 t, %1; cvt.u32.u64 %0, t; }" : "=r"(a) : "l"(p));
    return a;
}
__device__ __forceinline__ void cp_async16(uint32_t dst, const void* src) {
    asm volatile("cp.async.cg.shared.global [%0], [%1], 16;" :: "r"(dst), "l"(src));
}
__device__ __forceinline__ void cp_commit() {
    asm volatile("cp.async.commit_group;" ::: "memory");
}
template <int N>
__device__ __forceinline__ void cp_wait() {
    asm volatile("cp.async.wait_group %0;" :: "n"(N) : "memory");
}
__device__ __forceinline__ void ldsm4(uint32_t* r, uint32_t addr) {
    asm volatile("ldmatrix.sync.aligned.m8n8.x4.shared.b16 {%0,%1,%2,%3}, [%4];"
                 : "=r"(r[0]), "=r"(r[1]), "=r"(r[2]), "=r"(r[3]) : "r"(addr));
}
__device__ __forceinline__ void mma16816(float* c, const uint32_t* a,
                                         uint32_t b0, uint32_t b1) {
    asm volatile("mma.sync.aligned.m16n8k16.row.col.f32.bf16.bf16.f32 "
                 "{%0,%1,%2,%3}, {%4,%5,%6,%7}, {%8,%9}, {%0,%1,%2,%3};"
                 : "+f"(c[0]), "+f"(c[1]), "+f"(c[2]), "+f"(c[3])
                 : "r"(a[0]), "r"(a[1]), "r"(a[2]), "r"(a[3]), "r"(b0), "r"(b1));
}

// ---------------------------------------------------------------------------
// Pre-pass A: enc_states fp32 -> bf16 (RN)
// ---------------------------------------------------------------------------
__global__ void convert_enc(const float* __restrict__ enc) {
    size_t i = (size_t)blockIdx.x * blockDim.x + threadIdx.x;  // one float4 each
    float4 v = reinterpret_cast<const float4*>(enc)[i];
    __nv_bfloat162 p0 = __floats2bfloat162_rn(v.x, v.y);
    __nv_bfloat162 p1 = __floats2bfloat162_rn(v.z, v.w);
    uint2 u;
    u.x = *reinterpret_cast<uint32_t*>(&p0);
    u.y = *reinterpret_cast<uint32_t*>(&p1);
    reinterpret_cast<uint2*>(g_encb)[i] = u;
}

// ---------------------------------------------------------------------------
// Pre-pass B: W_enc [K,N] fp32 -> transposed K-major bf16 hi/lo pair
// ---------------------------------------------------------------------------
__global__ void convert_W(const float* __restrict__ W) {
    int n = blockIdx.x;
    int k = threadIdx.x;
    float w = W[(size_t)k * Dn + n];
    __nv_bfloat16 hi = __float2bfloat16_rn(w);
    __nv_bfloat16 lo = __float2bfloat16_rn(w - __bfloat162float(hi));
    g_WTh[(size_t)n * Dn + k] = hi;
    g_WTl[(size_t)n * Dn + k] = lo;
}

// ---------------------------------------------------------------------------
// decb[b,c] = b_dec[c] + b_enc[c] + dec_states[b,:] @ W_dec[:,c]
// grid (Bn, 4) x 256 threads: 128 CTAs (was 32 -> latency-starved)
// ---------------------------------------------------------------------------
__global__ void dech_kernel(const float* __restrict__ dec,
                            const float* __restrict__ Wdec,
                            const float* __restrict__ bdec,
                            const float* __restrict__ benc) {
    const int b   = blockIdx.x;
    const int c   = blockIdx.y * 256 + threadIdx.x;
    __shared__ float dsh[Dn];
    for (int k = threadIdx.x; k < Dn; k += 256) dsh[k] = dec[b * Dn + k];
    __syncthreads();
    float acc = bdec[c] + benc[c];
    #pragma unroll 8
    for (int k = 0; k < Dn; k++)
        acc = fmaf(dsh[k], Wdec[(size_t)k * Dn + c], acc);
    g_decb[b * Dn + c] = acc;
}

// ---------------------------------------------------------------------------
// HMMA fused score GEMM.
//  D[128,64] = A_bf16[128,K] @ (Bhi+Blo)[64,K]^T  (accumulated in fp32)
//  epilogue: rowsum of tanh(D + decb) * w_attn -> g_scores_part[tile_n][row]
//  8 warps in 4(M) x 2(N); each warp owns a 32x32 sub-tile.
//  SMEM rows padded to 40 bf16 (80 B): conflict-free ldmatrix.
//  __launch_bounds__(256,3): cap regs (~84) so 3 CTAs/SM fit (reg-limited at
//  128 regs we only got 2 CTAs -> occ 24.6%, tensor pipe 55%).
// ---------------------------------------------------------------------------
struct Stage {
    __nv_bfloat16 A[BM][40];
    __nv_bfloat16 Bh[BN][40];
    __nv_bfloat16 Bl[BN][40];
};

__global__ __launch_bounds__(256, 3)
void score_gemm_hmma(const float* __restrict__ wattn) {
    __shared__ __align__(16) Stage stg[2];
    __shared__ float s_db[BN], s_w[BN];
    __shared__ float rowsum[2][BM];

    const int tid  = threadIdx.x;
    const int wid  = tid >> 5;
    const int lane = tid & 31;
    const int wm   = wid >> 1;     // 0..3 : 32-row group
    const int wn   = wid & 1;      // 0..1 : 32-col group
    const int n0   = blockIdx.x * BN;   // x = col tile -> 16 CTAs share A in L2
    const int m0   = blockIdx.y * BM;
    const int b    = m0 >> 11;

    if (tid < BN) {
        s_db[tid] = g_decb[b * Dn + n0 + tid];
        s_w[tid]  = wattn[n0 + tid];
    }

    float acc[2][4][4];
    #pragma unroll
    for (int i = 0; i < 2; i++)
        #pragma unroll
        for (int j = 0; j < 4; j++)
            #pragma unroll
            for (int q = 0; q < 4; q++) acc[i][j][q] = 0.f;

    const __nv_bfloat16* __restrict__ Ab = g_encb + (size_t)m0 * Dn;

    auto load_chunk = [&](int c) {
        const int st = c & 1;
        const int k0 = c * BK;
        #pragma unroll
        for (int i = 0; i < 2; i++) {                 // A: 128 rows x 4 x 16B
            int seg = tid + i * 256;
            int r = seg >> 2, s = seg & 3;
            cp_async16(smem_u32(&stg[st].A[r][s * 8]),
                       Ab + (size_t)r * Dn + k0 + s * 8);
        }
        {                                             // Bh/Bl: 64 rows x 4 x 16B
            int r = tid >> 2, s = tid & 3;
            const size_t g = (size_t)(n0 + r) * Dn + k0 + s * 8;
            cp_async16(smem_u32(&stg[st].Bh[r][s * 8]), g_WTh + g);
            cp_async16(smem_u32(&stg[st].Bl[r][s * 8]), g_WTl + g);
        }
        cp_commit();
    };

    load_chunk(0);
    load_chunk(1);

    for (int c = 0; c < NCHUNK; c++) {
        if (c == NCHUNK - 1) cp_wait<0>(); else cp_wait<1>();
        __syncthreads();
        const Stage& S = stg[c & 1];

        #pragma unroll
        for (int kk = 0; kk < 2; kk++) {              // two k16 steps per chunk
            const int kb = kk * 16;
            // A frags: 2 x ldmatrix.x4 (rows wm*32 .. +31)
            uint32_t a[2][4];
            #pragma unroll
            for (int mi = 0; mi < 2; mi++) {
                int row = wm * 32 + mi * 16 + (lane & 15);
                int col = kb + (lane >> 4) * 8;
                ldsm4(a[mi], smem_u32(&S.A[row][col]));
            }
            // B frags (col-major [n][k]): per 16-col pair one x4 for hi and lo
            uint32_t bh[2][4], bl[2][4];
            const int quad = lane >> 3;
            #pragma unroll
            for (int p = 0; p < 2; p++) {
                int nrow = wn * 32 + p * 16 + ((quad & 2) ? 8 : 0) + (lane & 7);
                int kcol = kb + ((quad & 1) ? 8 : 0);
                ldsm4(bh[p], smem_u32(&S.Bh[nrow][kcol]));
                ldsm4(bl[p], smem_u32(&S.Bl[nrow][kcol]));
            }
            #pragma unroll
            for (int mi = 0; mi < 2; mi++)
                #pragma unroll
                for (int p = 0; p < 2; p++)
                    #pragma unroll
                    for (int sub = 0; sub < 2; sub++) {
                        int nf = p * 2 + sub;
                        mma16816(acc[mi][nf], a[mi], bh[p][sub * 2], bh[p][sub * 2 + 1]);
                        mma16816(acc[mi][nf], a[mi], bl[p][sub * 2], bl[p][sub * 2 + 1]);
                    }
        }
        __syncthreads();
        if (c + 2 < NCHUNK) load_chunk(c + 2);
    }

    // Epilogue: rowsum of tanh(acc + decb) * w_attn
    #pragma unroll
    for (int mi = 0; mi < 2; mi++) {
        float sl = 0.f, sh = 0.f;
        #pragma unroll
        for (int nf = 0; nf < 4; nf++) {
            int cb = wn * 32 + nf * 8 + (lane & 3) * 2;
            sl += tanhf(acc[mi][nf][0] + s_db[cb])     * s_w[cb]
                + tanhf(acc[mi][nf][1] + s_db[cb + 1]) * s_w[cb + 1];
            sh += tanhf(acc[mi][nf][2] + s_db[cb])     * s_w[cb]
                + tanhf(acc[mi][nf][3] + s_db[cb + 1]) * s_w[cb + 1];
        }
        sl += __shfl_xor_sync(0xffffffffu, sl, 1);
        sl += __shfl_xor_sync(0xffffffffu, sl, 2);
        sh += __shfl_xor_sync(0xffffffffu, sh, 1);
        sh += __shfl_xor_sync(0xffffffffu, sh, 2);
        if ((lane & 3) == 0) {
            int r = wm * 32 + mi * 16 + (lane >> 2);
            rowsum[wn][r]     = sl;
            rowsum[wn][r + 8] = sh;
        }
    }
    __syncthreads();
    if (tid < BM)
        g_scores_part[blockIdx.x * Mn + m0 + tid] = rowsum[0][tid] + rowsum[1][tid];
}

// ---------------------------------------------------------------------------
// Masked softmax per batch row; writes attn into d_out[32768 + b*2048 + s]
// ---------------------------------------------------------------------------
__global__ void softmax_kernel(const int* __restrict__ enc_len,
                               float* __restrict__ attn_out) {
    const int b = blockIdx.x;
    const int tid = threadIdx.x;
    __shared__ float red[256];
    __shared__ float sc[Sn];

    const int len = enc_len[b];

    float lmax = -INFINITY;
    for (int s = tid; s < Sn; s += 256) {
        float v = 0.f;
        #pragma unroll
        for (int ct = 0; ct < NTILES; ct++)
            v += g_scores_part[ct * Mn + b * Sn + s];
        sc[s] = v;
        if (s < len) lmax = fmaxf(lmax, v);
    }
    red[tid] = lmax;
    __syncthreads();
    for (int off = 128; off > 0; off >>= 1) {
        if (tid < off) red[tid] = fmaxf(red[tid], red[tid + off]);
        __syncthreads();
    }
    const float m = red[0];
    __syncthreads();

    float lsum = 0.f;
    for (int s = tid; s < Sn; s += 256) {
        float e = (s < len) ? expf(sc[s] - m) : 0.f;
        sc[s] = e;
        lsum += e;
    }
    red[tid] = lsum;
    __syncthreads();
    for (int off = 128; off > 0; off >>= 1) {
        if (tid < off) red[tid] += red[tid + off];
        __syncthreads();
    }
    const float inv = 1.f / red[0];
    __syncthreads();

    for (int s = tid; s < Sn; s += 256)
        attn_out[b * Sn + s] = sc[s] * inv;
}

// ---------------------------------------------------------------------------
// Context partials (fp32 enc_states for accuracy; near DRAM roofline already)
// ---------------------------------------------------------------------------
__global__ void context_kernel(const float* __restrict__ enc,
                               const float* __restrict__ attn) {
    const int ch = blockIdx.x;
    const int b = blockIdx.y;
    const int tid = threadIdx.x;
    const int d = tid * 4;
    __shared__ float wsh[128];
    if (tid < 128) wsh[tid] = attn[b * Sn + ch * 128 + tid];
    __syncthreads();

    float4 acc = make_float4(0.f, 0.f, 0.f, 0.f);
    const int s0 = ch * 128;
    for (int i = 0; i < 128; i++) {
        float w = wsh[i];
        float4 e = *reinterpret_cast<const float4*>(
            &enc[((size_t)b * Sn + s0 + i) * Dn + d]);
        acc.x = fmaf(w, e.x, acc.x);
        acc.y = fmaf(w, e.y, acc.y);
        acc.z = fmaf(w, e.z, acc.z);
        acc.w = fmaf(w, e.w, acc.w);
    }
    *reinterpret_cast<float4*>(&g_ctx_part[((size_t)ch * Bn + b) * Dn + d]) = acc;
}

// ---------------------------------------------------------------------------
// Output GEMM: grid (Bn, 4) x 256 threads (was 32 CTAs -> latency-starved)
// ---------------------------------------------------------------------------
__global__ void out_kernel(const float* __restrict__ Wout,
                           const float* __restrict__ bout,
                           float* __restrict__ out) {
    const int b = blockIdx.x;
    const int c = blockIdx.y * 256 + threadIdx.x;
    __shared__ float ctx[Dn];
    for (int k = threadIdx.x; k < Dn; k += 256) {
        float v = 0.f;
        #pragma unroll
        for (int ch = 0; ch < 16; ch++)
            v += g_ctx_part[((size_t)ch * Bn + b) * Dn + k];
        ctx[k] = v;
    }
    __syncthreads();
    float acc = bout[c];
    #pragma unroll 8
    for (int k = 0; k < Dn; k++)
        acc = fmaf(ctx[k], Wout[(size_t)k * Dn + c], acc);
    out[b * Dn + c] = acc;
}

// ---------------------------------------------------------------------------
// Launch
// ---------------------------------------------------------------------------
extern "C" void kernel_launch(void* const* d_in, const int* in_sizes, int n_in,
                              void* d_out, int out_size) {
    const float* enc   = (const float*)d_in[0];
    const float* dec   = (const float*)d_in[1];
    const float* Wenc  = (const float*)d_in[2];
    const float* benc  = (const float*)d_in[3];
    const float* Wdec  = (const float*)d_in[4];
    const float* bdec  = (const float*)d_in[5];
    const float* wattn = (const float*)d_in[6];
    const float* Wout  = (const float*)d_in[7];
    const float* bout  = (const float*)d_in[8];
    const int*   elen  = (const int*)d_in[9];

    float* out      = (float*)d_out;       // context [32*1024]
    float* attn_out = out + Bn * Dn;       // attn    [32*2048]

    convert_enc<<<(Mn * (Dn / 4)) / 256, 256>>>(enc);
    convert_W<<<Dn, Dn>>>(Wenc);
    dech_kernel<<<dim3(Bn, 4), 256>>>(dec, Wdec, bdec, benc);
    score_gemm_hmma<<<dim3(NTILES, Mn / BM), 256>>>(wattn);
    softmax_kernel<<<Bn, 256>>>(elen, attn_out);
    context_kernel<<<dim3(16, Bn), 256>>>(enc, attn_out);
    out_kernel<<<dim3(Bn, 4), 256>>>(Wout, bout, out);
}

// round 9
// speedup vs baseline: 4.5092x; 1.0321x over previous
#include <cuda_runtime.h>
#include <cuda_bf16.h>
#include <cstdint>
#include <math.h>

// Problem constants
#define Bn   32
#define Sn   2048
#define Dn   1024
#define Mn   (Bn * Sn)

// Score-GEMM tiling (mma.sync HMMA path — tcgen05 PTX is rejected by the
// harness's compute_103 PTX stage, so we use the arch-portable tensor path)
#define BM 256              // CTA rows   (8 warps: 4M x 2N, warp tile 64x32)
#define BN 64               // CTA cols
#define BK 32
#define NTILES (Dn / BN)    // 16 column tiles
#define NCHUNK (Dn / BK)    // 32 K chunks

// ---------------------------------------------------------------------------
// Scratch (static device globals; no allocation allowed)
// ---------------------------------------------------------------------------
__device__ float g_decb[Bn * Dn];                    // dec_h + b_dec + b_enc
__device__ float g_scores_part[NTILES * Mn];         // per-col-tile score partials
__device__ float g_ctx_part[16 * Bn * Dn];           // context partials
__device__ __nv_bfloat16 g_encb[(size_t)Mn * Dn];    // enc_states bf16 (128 MB)
__device__ __nv_bfloat16 g_WTh[Dn * Dn];             // W_enc^T hi (K-major: [n][k])
__device__ __nv_bfloat16 g_WTl[Dn * Dn];             // W_enc^T lo

// ---------------------------------------------------------------------------
// PTX helpers (sm_80-compatible only: cp.async, ldmatrix, mma.sync)
// ---------------------------------------------------------------------------
__device__ __forceinline__ uint32_t smem_u32(const void* p) {
    uint32_t a;
    asm("{ .reg .u64 t; cvta.to.shared.u64 t, %1; cvt.u32.u64 %0, t; }" : "=r"(a) : "l"(p));
    return a;
}
__device__ __forceinline__ void cp_async16(uint32_t dst, const void* src) {
    asm volatile("cp.async.cg.shared.global [%0], [%1], 16;" :: "r"(dst), "l"(src));
}
__device__ __forceinline__ void cp_commit() {
    asm volatile("cp.async.commit_group;" ::: "memory");
}
template <int N>
__device__ __forceinline__ void cp_wait() {
    asm volatile("cp.async.wait_group %0;" :: "n"(N) : "memory");
}
__device__ __forceinline__ void ldsm4(uint32_t* r, uint32_t addr) {
    asm volatile("ldmatrix.sync.aligned.m8n8.x4.shared.b16 {%0,%1,%2,%3}, [%4];"
                 : "=r"(r[0]), "=r"(r[1]), "=r"(r[2]), "=r"(r[3]) : "r"(addr));
}
__device__ __forceinline__ void mma16816(float* c, const uint32_t* a,
                                         uint32_t b0, uint32_t b1) {
    asm volatile("mma.sync.aligned.m16n8k16.row.col.f32.bf16.bf16.f32 "
                 "{%0,%1,%2,%3}, {%4,%5,%6,%7}, {%8,%9}, {%0,%1,%2,%3};"
                 : "+f"(c[0]), "+f"(c[1]), "+f"(c[2]), "+f"(c[3])
                 : "r"(a[0]), "r"(a[1]), "r"(a[2]), "r"(a[3]), "r"(b0), "r"(b1));
}

// ---------------------------------------------------------------------------
// Pre-pass A: enc_states fp32 -> bf16 (RN)
// ---------------------------------------------------------------------------
__global__ void convert_enc(const float* __restrict__ enc) {
    size_t i = (size_t)blockIdx.x * blockDim.x + threadIdx.x;  // one float4 each
    float4 v = reinterpret_cast<const float4*>(enc)[i];
    __nv_bfloat162 p0 = __floats2bfloat162_rn(v.x, v.y);
    __nv_bfloat162 p1 = __floats2bfloat162_rn(v.z, v.w);
    uint2 u;
    u.x = *reinterpret_cast<uint32_t*>(&p0);
    u.y = *reinterpret_cast<uint32_t*>(&p1);
    reinterpret_cast<uint2*>(g_encb)[i] = u;
}

// ---------------------------------------------------------------------------
// Pre-pass B: W_enc [K,N] fp32 -> transposed K-major bf16 hi/lo pair
// ---------------------------------------------------------------------------
__global__ void convert_W(const float* __restrict__ W) {
    int n = blockIdx.x;
    int k = threadIdx.x;
    float w = W[(size_t)k * Dn + n];
    __nv_bfloat16 hi = __float2bfloat16_rn(w);
    __nv_bfloat16 lo = __float2bfloat16_rn(w - __bfloat162float(hi));
    g_WTh[(size_t)n * Dn + k] = hi;
    g_WTl[(size_t)n * Dn + k] = lo;
}

// ---------------------------------------------------------------------------
// decb[b,c] = b_dec[c] + b_enc[c] + dec_states[b,:] @ W_dec[:,c]
// ---------------------------------------------------------------------------
__global__ void dech_kernel(const float* __restrict__ dec,
                            const float* __restrict__ Wdec,
                            const float* __restrict__ bdec,
                            const float* __restrict__ benc) {
    const int b   = blockIdx.x;
    const int c   = blockIdx.y * 256 + threadIdx.x;
    __shared__ float dsh[Dn];
    for (int k = threadIdx.x; k < Dn; k += 256) dsh[k] = dec[b * Dn + k];
    __syncthreads();
    float acc = bdec[c] + benc[c];
    #pragma unroll 8
    for (int k = 0; k < Dn; k++)
        acc = fmaf(dsh[k], Wdec[(size_t)k * Dn + c], acc);
    g_decb[b * Dn + c] = acc;
}

// ---------------------------------------------------------------------------
// HMMA fused score GEMM.
//  D[256,64] = A_bf16[256,K] @ (Bhi+Blo)[64,K]^T  (fp32 accum)
//  epilogue: rowsum of tanh(D + decb) * w_attn -> g_scores_part[tile_n][row]
//  8 warps, 4(M) x 2(N); warp tile 64x32 (was 32x32: MMA:LDSM 2.67 -> 4.0).
//  MMAs issued in independence batches: 16 hi (16 distinct accs), then 16 lo
//  (asm volatile order is program order -> old hi/lo adjacency made a RAW
//  chain every 2nd MMA; tensor pipe stuck at 54%).
//  SMEM rows padded to 40 bf16 (80 B): conflict-free ldmatrix.
// ---------------------------------------------------------------------------
struct Stage {
    __nv_bfloat16 A[BM][40];    // 20480 B
    __nv_bfloat16 Bh[BN][40];   //  5120 B
    __nv_bfloat16 Bl[BN][40];   //  5120 B
};
#define SMEM_BYTES (2 * (int)sizeof(Stage) + (BN + BN + 2 * BM) * 4)

__global__ __launch_bounds__(256)
void score_gemm_hmma(const float* __restrict__ wattn) {
    extern __shared__ char dsm[];
    Stage* stg    = reinterpret_cast<Stage*>(dsm);
    float* s_db   = reinterpret_cast<float*>(dsm + 2 * sizeof(Stage));
    float* s_w    = s_db + BN;
    float* rowsum = s_w + BN;                 // [2][BM]

    const int tid  = threadIdx.x;
    const int wid  = tid >> 5;
    const int lane = tid & 31;
    const int wm   = wid >> 1;     // 0..3 : 64-row group
    const int wn   = wid & 1;      // 0..1 : 32-col group
    const int n0   = blockIdx.x * BN;   // x = col tile -> CTAs share A in L2
    const int m0   = blockIdx.y * BM;
    const int b    = m0 >> 11;

    if (tid < BN) {
        s_db[tid] = g_decb[b * Dn + n0 + tid];
        s_w[tid]  = wattn[n0 + tid];
    }

    float acc[4][4][4];            // [mi][nf][frag] : 64 regs
    #pragma unroll
    for (int i = 0; i < 4; i++)
        #pragma unroll
        for (int j = 0; j < 4; j++)
            #pragma unroll
            for (int q = 0; q < 4; q++) acc[i][j][q] = 0.f;

    const __nv_bfloat16* __restrict__ Ab = g_encb + (size_t)m0 * Dn;

    auto load_chunk = [&](int c) {
        const int st = c & 1;
        const int k0 = c * BK;
        #pragma unroll
        for (int i = 0; i < 4; i++) {                 // A: 256 rows x 4 x 16B
            int seg = tid + i * 256;
            int r = seg >> 2, s = seg & 3;
            cp_async16(smem_u32(&stg[st].A[r][s * 8]),
                       Ab + (size_t)r * Dn + k0 + s * 8);
        }
        {                                             // Bh/Bl: 64 rows x 4 x 16B
            int r = tid >> 2, s = tid & 3;
            const size_t g = (size_t)(n0 + r) * Dn + k0 + s * 8;
            cp_async16(smem_u32(&stg[st].Bh[r][s * 8]), g_WTh + g);
            cp_async16(smem_u32(&stg[st].Bl[r][s * 8]), g_WTl + g);
        }
        cp_commit();
    };

    load_chunk(0);
    load_chunk(1);

    for (int c = 0; c < NCHUNK; c++) {
        if (c == NCHUNK - 1) cp_wait<0>(); else cp_wait<1>();
        __syncthreads();
        const Stage& S = stg[c & 1];

        #pragma unroll
        for (int kk = 0; kk < 2; kk++) {              // two k16 steps per chunk
            const int kb = kk * 16;
            // A frags: 4 x ldmatrix.x4 (rows wm*64 .. +63)
            uint32_t a[4][4];
            #pragma unroll
            for (int mi = 0; mi < 4; mi++) {
                int row = wm * 64 + mi * 16 + (lane & 15);
                int col = kb + (lane >> 4) * 8;
                ldsm4(a[mi], smem_u32(&S.A[row][col]));
            }
            // B frags (col-major [n][k]): per 16-col pair one x4 for hi and lo
            uint32_t bh[2][4], bl[2][4];
            const int quad = lane >> 3;
            #pragma unroll
            for (int p = 0; p < 2; p++) {
                int nrow = wn * 32 + p * 16 + ((quad & 2) ? 8 : 0) + (lane & 7);
                int kcol = kb + ((quad & 1) ? 8 : 0);
                ldsm4(bh[p], smem_u32(&S.Bh[nrow][kcol]));
                ldsm4(bl[p], smem_u32(&S.Bl[nrow][kcol]));
            }
            // hi batch: 16 independent MMAs
            #pragma unroll
            for (int mi = 0; mi < 4; mi++)
                #pragma unroll
                for (int nf = 0; nf < 4; nf++)
                    mma16816(acc[mi][nf], a[mi],
                             bh[nf >> 1][(nf & 1) * 2], bh[nf >> 1][(nf & 1) * 2 + 1]);
            // lo batch: 16 independent MMAs (RAW distance 16)
            #pragma unroll
            for (int mi = 0; mi < 4; mi++)
                #pragma unroll
                for (int nf = 0; nf < 4; nf++)
                    mma16816(acc[mi][nf], a[mi],
                             bl[nf >> 1][(nf & 1) * 2], bl[nf >> 1][(nf & 1) * 2 + 1]);
        }
        __syncthreads();
        if (c + 2 < NCHUNK) load_chunk(c + 2);
    }

    // Epilogue: rowsum of tanh(acc + decb) * w_attn
    // c-frag: c0,c1 -> row lane/4, cols 2*(lane%4)+{0,1}; c2,c3 -> row +8
    #pragma unroll
    for (int mi = 0; mi < 4; mi++) {
        float sl = 0.f, sh = 0.f;
        #pragma unroll
        for (int nf = 0; nf < 4; nf++) {
            int cb = wn * 32 + nf * 8 + (lane & 3) * 2;
            sl += tanhf(acc[mi][nf][0] + s_db[cb])     * s_w[cb]
                + tanhf(acc[mi][nf][1] + s_db[cb + 1]) * s_w[cb + 1];
            sh += tanhf(acc[mi][nf][2] + s_db[cb])     * s_w[cb]
                + tanhf(acc[mi][nf][3] + s_db[cb + 1]) * s_w[cb + 1];
        }
        sl += __shfl_xor_sync(0xffffffffu, sl, 1);
        sl += __shfl_xor_sync(0xffffffffu, sl, 2);
        sh += __shfl_xor_sync(0xffffffffu, sh, 1);
        sh += __shfl_xor_sync(0xffffffffu, sh, 2);
        if ((lane & 3) == 0) {
            int r = wm * 64 + mi * 16 + (lane >> 2);
            rowsum[wn * BM + r]     = sl;
            rowsum[wn * BM + r + 8] = sh;
        }
    }
    __syncthreads();
    g_scores_part[blockIdx.x * Mn + m0 + tid] = rowsum[tid] + rowsum[BM + tid];
}

// ---------------------------------------------------------------------------
// Masked softmax per batch row; writes attn into d_out[32768 + b*2048 + s]
// ---------------------------------------------------------------------------
__global__ void softmax_kernel(const int* __restrict__ enc_len,
                               float* __restrict__ attn_out) {
    const int b = blockIdx.x;
    const int tid = threadIdx.x;
    __shared__ float red[256];
    __shared__ float sc[Sn];

    const int len = enc_len[b];

    float lmax = -INFINITY;
    for (int s = tid; s < Sn; s += 256) {
        float v = 0.f;
        #pragma unroll
        for (int ct = 0; ct < NTILES; ct++)
            v += g_scores_part[ct * Mn + b * Sn + s];
        sc[s] = v;
        if (s < len) lmax = fmaxf(lmax, v);
    }
    red[tid] = lmax;
    __syncthreads();
    for (int off = 128; off > 0; off >>= 1) {
        if (tid < off) red[tid] = fmaxf(red[tid], red[tid + off]);
        __syncthreads();
    }
    const float m = red[0];
    __syncthreads();

    float lsum = 0.f;
    for (int s = tid; s < Sn; s += 256) {
        float e = (s < len) ? expf(sc[s] - m) : 0.f;
        sc[s] = e;
        lsum += e;
    }
    red[tid] = lsum;
    __syncthreads();
    for (int off = 128; off > 0; off >>= 1) {
        if (tid < off) red[tid] += red[tid + off];
        __syncthreads();
    }
    const float inv = 1.f / red[0];
    __syncthreads();

    for (int s = tid; s < Sn; s += 256)
        attn_out[b * Sn + s] = sc[s] * inv;
}

// ---------------------------------------------------------------------------
// Context partials (fp32 enc_states for accuracy; near DRAM roofline already)
// ---------------------------------------------------------------------------
__global__ void context_kernel(const float* __restrict__ enc,
                               const float* __restrict__ attn) {
    const int ch = blockIdx.x;
    const int b = blockIdx.y;
    const int tid = threadIdx.x;
    const int d = tid * 4;
    __shared__ float wsh[128];
    if (tid < 128) wsh[tid] = attn[b * Sn + ch * 128 + tid];
    __syncthreads();

    float4 acc = make_float4(0.f, 0.f, 0.f, 0.f);
    const int s0 = ch * 128;
    for (int i = 0; i < 128; i++) {
        float w = wsh[i];
        float4 e = *reinterpret_cast<const float4*>(
            &enc[((size_t)b * Sn + s0 + i) * Dn + d]);
        acc.x = fmaf(w, e.x, acc.x);
        acc.y = fmaf(w, e.y, acc.y);
        acc.z = fmaf(w, e.z, acc.z);
        acc.w = fmaf(w, e.w, acc.w);
    }
    *reinterpret_cast<float4*>(&g_ctx_part[((size_t)ch * Bn + b) * Dn + d]) = acc;
}

// ---------------------------------------------------------------------------
// Output GEMM
// ---------------------------------------------------------------------------
__global__ void out_kernel(const float* __restrict__ Wout,
                           const float* __restrict__ bout,
                           float* __restrict__ out) {
    const int b = blockIdx.x;
    const int c = blockIdx.y * 256 + threadIdx.x;
    __shared__ float ctx[Dn];
    for (int k = threadIdx.x; k < Dn; k += 256) {
        float v = 0.f;
        #pragma unroll
        for (int ch = 0; ch < 16; ch++)
            v += g_ctx_part[((size_t)ch * Bn + b) * Dn + k];
        ctx[k] = v;
    }
    __syncthreads();
    float acc = bout[c];
    #pragma unroll 8
    for (int k = 0; k < Dn; k++)
        acc = fmaf(ctx[k], Wout[(size_t)k * Dn + c], acc);
    out[b * Dn + c] = acc;
}

// ---------------------------------------------------------------------------
// Launch
// ---------------------------------------------------------------------------
extern "C" void kernel_launch(void* const* d_in, const int* in_sizes, int n_in,
                              void* d_out, int out_size) {
    const float* enc   = (const float*)d_in[0];
    const float* dec   = (const float*)d_in[1];
    const float* Wenc  = (const float*)d_in[2];
    const float* benc  = (const float*)d_in[3];
    const float* Wdec  = (const float*)d_in[4];
    const float* bdec  = (const float*)d_in[5];
    const float* wattn = (const float*)d_in[6];
    const float* Wout  = (const float*)d_in[7];
    const float* bout  = (const float*)d_in[8];
    const int*   elen  = (const int*)d_in[9];

    float* out      = (float*)d_out;       // context [32*1024]
    float* attn_out = out + Bn * Dn;       // attn    [32*2048]

    cudaFuncSetAttribute(score_gemm_hmma,
                         cudaFuncAttributeMaxDynamicSharedMemorySize, SMEM_BYTES);

    convert_enc<<<(Mn * (Dn / 4)) / 256, 256>>>(enc);
    convert_W<<<Dn, Dn>>>(Wenc);
    dech_kernel<<<dim3(Bn, 4), 256>>>(dec, Wdec, bdec, benc);
    score_gemm_hmma<<<dim3(NTILES, Mn / BM), 256, SMEM_BYTES>>>(wattn);
    softmax_kernel<<<Bn, 256>>>(elen, attn_out);
    context_kernel<<<dim3(16, Bn), 256>>>(enc, attn_out);
    out_kernel<<<dim3(Bn, 4), 256>>>(Wout, bout, out);
}

// round 11
// speedup vs baseline: 5.7424x; 1.2735x over previous
#include <cuda_runtime.h>
#include <cuda_fp16.h>
#include <cstdint>
#include <math.h>

// Problem constants
#define Bn   32
#define Sn   2048
#define Dn   1024
#define Mn   (Bn * Sn)

// Score-GEMM tiling (mma.sync HMMA path — tcgen05 PTX is rejected by the
// harness's compute_103 PTX stage, so we use the arch-portable tensor path)
// fp16 single-pass: fp16's 11-bit mantissa replaces the bf16 hi/lo double-pass
// (half the MMA instructions for BETTER accuracy; inputs are N(0,1) and
// 0.02*N(0,1) — comfortably inside fp16 range).
#define BM 256              // CTA rows   (8 warps: 4M x 2N, warp tile 64x32)
#define BN 64               // CTA cols
#define BK 32
#define NTILES (Dn / BN)    // 16 column tiles
#define NCHUNK (Dn / BK)    // 32 K chunks

// ---------------------------------------------------------------------------
// Scratch (static device globals; no allocation allowed)
// ---------------------------------------------------------------------------
__device__ float g_decb[Bn * Dn];                    // dec_h + b_dec + b_enc
__device__ float g_scores_part[NTILES * Mn];         // per-col-tile score partials
__device__ float g_ctx_part[16 * Bn * Dn];           // context partials
__device__ __half g_ench[(size_t)Mn * Dn];           // enc_states fp16 (128 MB)
__device__ __half g_WT[Dn * Dn];                     // W_enc^T fp16 (K-major: [n][k])

// ---------------------------------------------------------------------------
// PTX helpers (sm_80-compatible only: cp.async, ldmatrix, mma.sync)
// ---------------------------------------------------------------------------
__device__ __forceinline__ uint32_t smem_u32(const void* p) {
    uint32_t a;
    asm("{ .reg .u64 t; cvta.to.shared.u64 t, %1; cvt.u32.u64 %0, t; }" : "=r"(a) : "l"(p));
    return a;
}
__device__ __forceinline__ void cp_async16(uint32_t dst, const void* src) {
    asm volatile("cp.async.cg.shared.global [%0], [%1], 16;" :: "r"(dst), "l"(src));
}
__device__ __forceinline__ void cp_commit() {
    asm volatile("cp.async.commit_group;" ::: "memory");
}
template <int N>
__device__ __forceinline__ void cp_wait() {
    asm volatile("cp.async.wait_group %0;" :: "n"(N) : "memory");
}
__device__ __forceinline__ void ldsm4(uint32_t* r, uint32_t addr) {
    asm volatile("ldmatrix.sync.aligned.m8n8.x4.shared.b16 {%0,%1,%2,%3}, [%4];"
                 : "=r"(r[0]), "=r"(r[1]), "=r"(r[2]), "=r"(r[3]) : "r"(addr));
}
__device__ __forceinline__ void mma16816(float* c, const uint32_t* a,
                                         uint32_t b0, uint32_t b1) {
    asm volatile("mma.sync.aligned.m16n8k16.row.col.f32.f16.f16.f32 "
                 "{%0,%1,%2,%3}, {%4,%5,%6,%7}, {%8,%9}, {%0,%1,%2,%3};"
                 : "+f"(c[0]), "+f"(c[1]), "+f"(c[2]), "+f"(c[3])
                 : "r"(a[0]), "r"(a[1]), "r"(a[2]), "r"(a[3]), "r"(b0), "r"(b1));
}

// ---------------------------------------------------------------------------
// Pre-pass A: enc_states fp32 -> fp16 (RN)
// ---------------------------------------------------------------------------
__global__ void convert_enc(const float* __restrict__ enc) {
    size_t i = (size_t)blockIdx.x * blockDim.x + threadIdx.x;  // one float4 each
    float4 v = reinterpret_cast<const float4*>(enc)[i];
    __half2 p0 = __floats2half2_rn(v.x, v.y);
    __half2 p1 = __floats2half2_rn(v.z, v.w);
    uint2 u;
    u.x = *reinterpret_cast<uint32_t*>(&p0);
    u.y = *reinterpret_cast<uint32_t*>(&p1);
    reinterpret_cast<uint2*>(g_ench)[i] = u;
}

// ---------------------------------------------------------------------------
// Pre-pass B: W_enc [K,N] fp32 -> transposed K-major fp16
// ---------------------------------------------------------------------------
__global__ void convert_W(const float* __restrict__ W) {
    int n = blockIdx.x;
    int k = threadIdx.x;
    g_WT[(size_t)n * Dn + k] = __float2half_rn(W[(size_t)k * Dn + n]);
}

// ---------------------------------------------------------------------------
// decb[b,c] = b_dec[c] + b_enc[c] + dec_states[b,:] @ W_dec[:,c]
// ---------------------------------------------------------------------------
__global__ void dech_kernel(const float* __restrict__ dec,
                            const float* __restrict__ Wdec,
                            const float* __restrict__ bdec,
                            const float* __restrict__ benc) {
    const int b   = blockIdx.x;
    const int c   = blockIdx.y * 256 + threadIdx.x;
    __shared__ float dsh[Dn];
    for (int k = threadIdx.x; k < Dn; k += 256) dsh[k] = dec[b * Dn + k];
    __syncthreads();
    float acc = bdec[c] + benc[c];
    #pragma unroll 8
    for (int k = 0; k < Dn; k++)
        acc = fmaf(dsh[k], Wdec[(size_t)k * Dn + c], acc);
    g_decb[b * Dn + c] = acc;
}

// ---------------------------------------------------------------------------
// HMMA fused score GEMM (fp16 single-pass).
//  D[256,64] = A_fp16[256,K] @ B_fp16[64,K]^T  (fp32 accum)
//  epilogue: rowsum of tanh(D + decb) * w_attn -> g_scores_part[tile_n][row]
//  8 warps, 4(M) x 2(N); warp tile 64x32.
//  16-MMA independence batches; SMEM rows padded to 40 halves (80 B):
//  conflict-free ldmatrix.
// ---------------------------------------------------------------------------
struct Stage {
    __half A[BM][40];    // 20480 B
    __half B[BN][40];    //  5120 B
};
#define SMEM_BYTES (2 * (int)sizeof(Stage) + (BN + BN + 2 * BM) * 4)

__global__ __launch_bounds__(256)
void score_gemm_hmma(const float* __restrict__ wattn) {
    extern __shared__ char dsm[];
    Stage* stg    = reinterpret_cast<Stage*>(dsm);
    float* s_db   = reinterpret_cast<float*>(dsm + 2 * sizeof(Stage));
    float* s_w    = s_db + BN;
    float* rowsum = s_w + BN;                 // [2][BM]

    const int tid  = threadIdx.x;
    const int wid  = tid >> 5;
    const int lane = tid & 31;
    const int wm   = wid >> 1;     // 0..3 : 64-row group
    const int wn   = wid & 1;      // 0..1 : 32-col group
    const int n0   = blockIdx.x * BN;   // x = col tile -> CTAs share A in L2
    const int m0   = blockIdx.y * BM;
    const int b    = m0 >> 11;

    if (tid < BN) {
        s_db[tid] = g_decb[b * Dn + n0 + tid];
        s_w[tid]  = wattn[n0 + tid];
    }

    float acc[4][4][4];            // [mi][nf][frag] : 64 regs
    #pragma unroll
    for (int i = 0; i < 4; i++)
        #pragma unroll
        for (int j = 0; j < 4; j++)
            #pragma unroll
            for (int q = 0; q < 4; q++) acc[i][j][q] = 0.f;

    const __half* __restrict__ Ab = g_ench + (size_t)m0 * Dn;

    auto load_chunk = [&](int c) {
        const int st = c & 1;
        const int k0 = c * BK;
        #pragma unroll
        for (int i = 0; i < 4; i++) {                 // A: 256 rows x 4 x 16B
            int seg = tid + i * 256;
            int r = seg >> 2, s = seg & 3;
            cp_async16(smem_u32(&stg[st].A[r][s * 8]),
                       Ab + (size_t)r * Dn + k0 + s * 8);
        }
        {                                             // B: 64 rows x 4 x 16B
            int r = tid >> 2, s = tid & 3;
            cp_async16(smem_u32(&stg[st].B[r][s * 8]),
                       g_WT + (size_t)(n0 + r) * Dn + k0 + s * 8);
        }
        cp_commit();
    };

    load_chunk(0);
    load_chunk(1);

    for (int c = 0; c < NCHUNK; c++) {
        if (c == NCHUNK - 1) cp_wait<0>(); else cp_wait<1>();
        __syncthreads();
        const Stage& S = stg[c & 1];

        #pragma unroll
        for (int kk = 0; kk < 2; kk++) {              // two k16 steps per chunk
            const int kb = kk * 16;
            // A frags: 4 x ldmatrix.x4 (rows wm*64 .. +63)
            uint32_t a[4][4];
            #pragma unroll
            for (int mi = 0; mi < 4; mi++) {
                int row = wm * 64 + mi * 16 + (lane & 15);
                int col = kb + (lane >> 4) * 8;
                ldsm4(a[mi], smem_u32(&S.A[row][col]));
            }
            // B frags (col-major [n][k]): one x4 per 16-col pair
            uint32_t bf[2][4];
            const int quad = lane >> 3;
            #pragma unroll
            for (int p = 0; p < 2; p++) {
                int nrow = wn * 32 + p * 16 + ((quad & 2) ? 8 : 0) + (lane & 7);
                int kcol = kb + ((quad & 1) ? 8 : 0);
                ldsm4(bf[p], smem_u32(&S.B[nrow][kcol]));
            }
            // 16 independent MMAs (16 distinct accumulators)
            #pragma unroll
            for (int mi = 0; mi < 4; mi++)
                #pragma unroll
                for (int nf = 0; nf < 4; nf++)
                    mma16816(acc[mi][nf], a[mi],
                             bf[nf >> 1][(nf & 1) * 2], bf[nf >> 1][(nf & 1) * 2 + 1]);
        }
        __syncthreads();
        if (c + 2 < NCHUNK) load_chunk(c + 2);
    }

    // Epilogue: rowsum of tanh(acc + decb) * w_attn
    // c-frag: c0,c1 -> row lane/4, cols 2*(lane%4)+{0,1}; c2,c3 -> row +8
    #pragma unroll
    for (int mi = 0; mi < 4; mi++) {
        float sl = 0.f, sh = 0.f;
        #pragma unroll
        for (int nf = 0; nf < 4; nf++) {
            int cb = wn * 32 + nf * 8 + (lane & 3) * 2;
            sl += tanhf(acc[mi][nf][0] + s_db[cb])     * s_w[cb]
                + tanhf(acc[mi][nf][1] + s_db[cb + 1]) * s_w[cb + 1];
            sh += tanhf(acc[mi][nf][2] + s_db[cb])     * s_w[cb]
                + tanhf(acc[mi][nf][3] + s_db[cb + 1]) * s_w[cb + 1];
        }
        sl += __shfl_xor_sync(0xffffffffu, sl, 1);
        sl += __shfl_xor_sync(0xffffffffu, sl, 2);
        sh += __shfl_xor_sync(0xffffffffu, sh, 1);
        sh += __shfl_xor_sync(0xffffffffu, sh, 2);
        if ((lane & 3) == 0) {
            int r = wm * 64 + mi * 16 + (lane >> 2);
            rowsum[wn * BM + r]     = sl;
            rowsum[wn * BM + r + 8] = sh;
        }
    }
    __syncthreads();
    g_scores_part[blockIdx.x * Mn + m0 + tid] = rowsum[tid] + rowsum[BM + tid];
}

// ---------------------------------------------------------------------------
// Masked softmax per batch row; writes attn into d_out[32768 + b*2048 + s]
// ---------------------------------------------------------------------------
__global__ void softmax_kernel(const int* __restrict__ enc_len,
                               float* __restrict__ attn_out) {
    const int b = blockIdx.x;
    const int tid = threadIdx.x;
    __shared__ float red[256];
    __shared__ float sc[Sn];

    const int len = enc_len[b];

    float lmax = -INFINITY;
    for (int s = tid; s < Sn; s += 256) {
        float v = 0.f;
        #pragma unroll
        for (int ct = 0; ct < NTILES; ct++)
            v += g_scores_part[ct * Mn + b * Sn + s];
        sc[s] = v;
        if (s < len) lmax = fmaxf(lmax, v);
    }
    red[tid] = lmax;
    __syncthreads();
    for (int off = 128; off > 0; off >>= 1) {
        if (tid < off) red[tid] = fmaxf(red[tid], red[tid + off]);
        __syncthreads();
    }
    const float m = red[0];
    __syncthreads();

    float lsum = 0.f;
    for (int s = tid; s < Sn; s += 256) {
        float e = (s < len) ? expf(sc[s] - m) : 0.f;
        sc[s] = e;
        lsum += e;
    }
    red[tid] = lsum;
    __syncthreads();
    for (int off = 128; off > 0; off >>= 1) {
        if (tid < off) red[tid] += red[tid + off];
        __syncthreads();
    }
    const float inv = 1.f / red[0];
    __syncthreads();

    for (int s = tid; s < Sn; s += 256)
        attn_out[b * Sn + s] = sc[s] * inv;
}

// ---------------------------------------------------------------------------
// Context partials (fp32 enc_states for accuracy; near DRAM roofline already)
// ---------------------------------------------------------------------------
__global__ void context_kernel(const float* __restrict__ enc,
                               const float* __restrict__ attn) {
    const int ch = blockIdx.x;
    const int b = blockIdx.y;
    const int tid = threadIdx.x;
    const int d = tid * 4;
    __shared__ float wsh[128];
    if (tid < 128) wsh[tid] = attn[b * Sn + ch * 128 + tid];
    __syncthreads();

    float4 acc = make_float4(0.f, 0.f, 0.f, 0.f);
    const int s0 = ch * 128;
    for (int i = 0; i < 128; i++) {
        float w = wsh[i];
        float4 e = *reinterpret_cast<const float4*>(
            &enc[((size_t)b * Sn + s0 + i) * Dn + d]);
        acc.x = fmaf(w, e.x, acc.x);
        acc.y = fmaf(w, e.y, acc.y);
        acc.z = fmaf(w, e.z, acc.z);
        acc.w = fmaf(w, e.w, acc.w);
    }
    *reinterpret_cast<float4*>(&g_ctx_part[((size_t)ch * Bn + b) * Dn + d]) = acc;
}

// ---------------------------------------------------------------------------
// Output GEMM
// ---------------------------------------------------------------------------
__global__ void out_kernel(const float* __restrict__ Wout,
                           const float* __restrict__ bout,
                           float* __restrict__ out) {
    const int b = blockIdx.x;
    const int c = blockIdx.y * 256 + threadIdx.x;
    __shared__ float ctx[Dn];
    for (int k = threadIdx.x; k < Dn; k += 256) {
        float v = 0.f;
        #pragma unroll
        for (int ch = 0; ch < 16; ch++)
            v += g_ctx_part[((size_t)ch * Bn + b) * Dn + k];
        ctx[k] = v;
    }
    __syncthreads();
    float acc = bout[c];
    #pragma unroll 8
    for (int k = 0; k < Dn; k++)
        acc = fmaf(ctx[k], Wout[(size_t)k * Dn + c], acc);
    out[b * Dn + c] = acc;
}

// ---------------------------------------------------------------------------
// Launch
// ---------------------------------------------------------------------------
extern "C" void kernel_launch(void* const* d_in, const int* in_sizes, int n_in,
                              void* d_out, int out_size) {
    const float* enc   = (const float*)d_in[0];
    const float* dec   = (const float*)d_in[1];
    const float* Wenc  = (const float*)d_in[2];
    const float* benc  = (const float*)d_in[3];
    const float* Wdec  = (const float*)d_in[4];
    const float* bdec  = (const float*)d_in[5];
    const float* wattn = (const float*)d_in[6];
    const float* Wout  = (const float*)d_in[7];
    const float* bout  = (const float*)d_in[8];
    const int*   elen  = (const int*)d_in[9];

    float* out      = (float*)d_out;       // context [32*1024]
    float* attn_out = out + Bn * Dn;       // attn    [32*2048]

    cudaFuncSetAttribute(score_gemm_hmma,
                         cudaFuncAttributeMaxDynamicSharedMemorySize, SMEM_BYTES);

    convert_enc<<<(Mn * (Dn / 4)) / 256, 256>>>(enc);
    convert_W<<<Dn, Dn>>>(Wenc);
    dech_kernel<<<dim3(Bn, 4), 256>>>(dec, Wdec, bdec, benc);
    score_gemm_hmma<<<dim3(NTILES, Mn / BM), 256, SMEM_BYTES>>>(wattn);
    softmax_kernel<<<Bn, 256>>>(elen, attn_out);
    context_kernel<<<dim3(16, Bn), 256>>>(enc, attn_out);
    out_kernel<<<dim3(Bn, 4), 256>>>(Wout, bout, out);
}

// round 12
// speedup vs baseline: 6.9266x; 1.2062x over previous
#include <cuda_runtime.h>
#include <cuda_fp16.h>
#include <cstdint>
#include <math.h>

// Problem constants
#define Bn   32
#define Sn   2048
#define Dn   1024
#define Mn   (Bn * Sn)

// Score-GEMM tiling (mma.sync HMMA path — tcgen05 PTX is rejected by the
// harness's compute_103 PTX stage, so we use the arch-portable tensor path)
#define BM 256              // CTA rows   (8 warps: 4M x 2N, warp tile 64x32)
#define BN 64               // CTA cols
#define BK 64               // K per chunk (was 32: halves sync/loop overhead)
#define NTILES (Dn / BN)    // 16 column tiles
#define NCHUNK (Dn / BK)    // 16 chunks

#define ROWP 72             // SMEM row stride in halves (144 B = 36 banks ≡ 4
                            // mod 32 -> ldmatrix phases conflict-free)

// ---------------------------------------------------------------------------
// Scratch (static device globals; no allocation allowed)
// ---------------------------------------------------------------------------
__device__ float g_decb[Bn * Dn];                    // dec_h + b_dec + b_enc
__device__ float g_scores_part[NTILES * Mn];         // per-col-tile score partials
__device__ float g_ctx_part[16 * Bn * Dn];           // context partials
__device__ __half g_ench[(size_t)Mn * Dn];           // enc_states fp16 (128 MB)
__device__ __half g_WT[Dn * Dn];                     // W_enc^T fp16 (K-major: [n][k])

// ---------------------------------------------------------------------------
// PTX helpers (sm_80-compatible only: cp.async, ldmatrix, mma.sync)
// ---------------------------------------------------------------------------
__device__ __forceinline__ uint32_t smem_u32(const void* p) {
    uint32_t a;
    asm("{ .reg .u64 t; cvta.to.shared.u64 t, %1; cvt.u32.u64 %0, t; }" : "=r"(a) : "l"(p));
    return a;
}
__device__ __forceinline__ void cp_async16(uint32_t dst, const void* src) {
    asm volatile("cp.async.cg.shared.global [%0], [%1], 16;" :: "r"(dst), "l"(src));
}
__device__ __forceinline__ void cp_commit() {
    asm volatile("cp.async.commit_group;" ::: "memory");
}
template <int N>
__device__ __forceinline__ void cp_wait() {
    asm volatile("cp.async.wait_group %0;" :: "n"(N) : "memory");
}
__device__ __forceinline__ void ldsm4(uint32_t* r, uint32_t addr) {
    asm volatile("ldmatrix.sync.aligned.m8n8.x4.shared.b16 {%0,%1,%2,%3}, [%4];"
                 : "=r"(r[0]), "=r"(r[1]), "=r"(r[2]), "=r"(r[3]) : "r"(addr));
}
__device__ __forceinline__ void mma16816(float* c, const uint32_t* a,
                                         uint32_t b0, uint32_t b1) {
    asm volatile("mma.sync.aligned.m16n8k16.row.col.f32.f16.f16.f32 "
                 "{%0,%1,%2,%3}, {%4,%5,%6,%7}, {%8,%9}, {%0,%1,%2,%3};"
                 : "+f"(c[0]), "+f"(c[1]), "+f"(c[2]), "+f"(c[3])
                 : "r"(a[0]), "r"(a[1]), "r"(a[2]), "r"(a[3]), "r"(b0), "r"(b1));
}

// ---------------------------------------------------------------------------
// Pre-pass A: enc_states fp32 -> fp16 (RN)
// ---------------------------------------------------------------------------
__global__ void convert_enc(const float* __restrict__ enc) {
    size_t i = (size_t)blockIdx.x * blockDim.x + threadIdx.x;  // one float4 each
    float4 v = reinterpret_cast<const float4*>(enc)[i];
    __half2 p0 = __floats2half2_rn(v.x, v.y);
    __half2 p1 = __floats2half2_rn(v.z, v.w);
    uint2 u;
    u.x = *reinterpret_cast<uint32_t*>(&p0);
    u.y = *reinterpret_cast<uint32_t*>(&p1);
    reinterpret_cast<uint2*>(g_ench)[i] = u;
}

// ---------------------------------------------------------------------------
// Pre-pass B: W_enc [K,N] fp32 -> transposed K-major fp16
// ---------------------------------------------------------------------------
__global__ void convert_W(const float* __restrict__ W) {
    int n = blockIdx.x;
    int k = threadIdx.x;
    g_WT[(size_t)n * Dn + k] = __float2half_rn(W[(size_t)k * Dn + n]);
}

// ---------------------------------------------------------------------------
// decb[b,c] = b_dec[c] + b_enc[c] + dec_states[b,:] @ W_dec[:,c]
// ---------------------------------------------------------------------------
__global__ void dech_kernel(const float* __restrict__ dec,
                            const float* __restrict__ Wdec,
                            const float* __restrict__ bdec,
                            const float* __restrict__ benc) {
    const int b   = blockIdx.x;
    const int c   = blockIdx.y * 256 + threadIdx.x;
    __shared__ float dsh[Dn];
    for (int k = threadIdx.x; k < Dn; k += 256) dsh[k] = dec[b * Dn + k];
    __syncthreads();
    float acc = bdec[c] + benc[c];
    #pragma unroll 8
    for (int k = 0; k < Dn; k++)
        acc = fmaf(dsh[k], Wdec[(size_t)k * Dn + c], acc);
    g_decb[b * Dn + c] = acc;
}

// ---------------------------------------------------------------------------
// HMMA fused score GEMM (fp16 single-pass, BK=64, hoisted addressing).
//  D[256,64] = A_fp16[256,K] @ B_fp16[64,K]^T  (fp32 accum)
//  epilogue: rowsum of tanh(D + decb) * w_attn -> g_scores_part[tile_n][row]
//  8 warps, 4(M) x 2(N); warp tile 64x32; 16-MMA independence batches.
//  All cp.async / ldmatrix addresses are base + compile-time-constant offsets
//  (256 threads | 8 segs/row -> seg split is i*32 rows), attacking the 28.9%
//  ALU issue share seen in R11.
// ---------------------------------------------------------------------------
struct Stage {
    __half A[BM][ROWP];    // 36864 B
    __half B[BN][ROWP];    //  9216 B
};
#define B_OFF  (BM * ROWP * 2)             // byte offset of B within a stage
#define SMEM_BYTES (2 * (int)sizeof(Stage) + (BN + BN + 2 * BM) * 4)

__global__ __launch_bounds__(256)
void score_gemm_hmma(const float* __restrict__ wattn) {
    extern __shared__ char dsm[];
    Stage* stg    = reinterpret_cast<Stage*>(dsm);
    float* s_db   = reinterpret_cast<float*>(dsm + 2 * sizeof(Stage));
    float* s_w    = s_db + BN;
    float* rowsum = s_w + BN;                 // [2][BM]

    const int tid  = threadIdx.x;
    const int wid  = tid >> 5;
    const int lane = tid & 31;
    const int wm   = wid >> 1;     // 0..3 : 64-row group
    const int wn   = wid & 1;      // 0..1 : 32-col group
    const int n0   = blockIdx.x * BN;   // x = col tile -> CTAs share A in L2
    const int m0   = blockIdx.y * BM;
    const int b    = m0 >> 11;

    if (tid < BN) {
        s_db[tid] = g_decb[b * Dn + n0 + tid];
        s_w[tid]  = wattn[n0 + tid];
    }

    float acc[4][4][4];            // [mi][nf][frag] : 64 regs
    #pragma unroll
    for (int i = 0; i < 4; i++)
        #pragma unroll
        for (int j = 0; j < 4; j++)
            #pragma unroll
            for (int q = 0; q < 4; q++) acc[i][j][q] = 0.f;

    // ---- hoisted loader addressing (s8 identical across i; rows step 32) ----
    const int s8 = (tid & 7) * 8;             // half offset within 64-half row
    const int r0 = tid >> 3;                  // 0..31
    const __half* aSrc = g_ench + (size_t)m0 * Dn + (size_t)r0 * Dn + s8;
    const __half* bSrc = g_WT + (size_t)(n0 + r0) * Dn + s8;
    const uint32_t stg0 = smem_u32(&stg[0]);
    const uint32_t stg1 = smem_u32(&stg[1]);
    const uint32_t aDst = r0 * (ROWP * 2) + s8 * 2;           // within stage
    const uint32_t bDst = B_OFF + r0 * (ROWP * 2) + s8 * 2;

    auto load_chunk = [&](int c) {
        const uint32_t base = (c & 1) ? stg1 : stg0;
        const int k0 = c * BK;
        #pragma unroll
        for (int i = 0; i < 8; i++)           // A: 8 x 32 rows
            cp_async16(base + aDst + i * (32 * ROWP * 2),
                       aSrc + k0 + (size_t)i * 32 * Dn);
        #pragma unroll
        for (int i = 0; i < 2; i++)           // B: 2 x 32 rows
            cp_async16(base + bDst + i * (32 * ROWP * 2),
                       bSrc + k0 + (size_t)i * 32 * Dn);
        cp_commit();
    };

    // ---- hoisted ldmatrix addressing ----
    const uint32_t aLd = (wm * 64 + (lane & 15)) * (ROWP * 2) + (lane >> 4) * 16;
    const int quad = lane >> 3;
    const uint32_t bLd = B_OFF
        + (wn * 32 + ((quad & 2) ? 8 : 0) + (lane & 7)) * (ROWP * 2)
        + ((quad & 1) ? 16 : 0);

    load_chunk(0);
    load_chunk(1);

    for (int c = 0; c < NCHUNK; c++) {
        if (c == NCHUNK - 1) cp_wait<0>(); else cp_wait<1>();
        __syncthreads();
        const uint32_t base = (c & 1) ? stg1 : stg0;

        #pragma unroll
        for (int kk = 0; kk < 4; kk++) {              // four k16 steps per chunk
            const uint32_t kboff = kk * 32;           // kb*2 bytes
            uint32_t a[4][4];
            #pragma unroll
            for (int mi = 0; mi < 4; mi++)
                ldsm4(a[mi], base + aLd + mi * (16 * ROWP * 2) + kboff);
            uint32_t bf[2][4];
            #pragma unroll
            for (int p = 0; p < 2; p++)
                ldsm4(bf[p], base + bLd + p * (16 * ROWP * 2) + kboff);
            // 16 independent MMAs (16 distinct accumulators)
            #pragma unroll
            for (int mi = 0; mi < 4; mi++)
                #pragma unroll
                for (int nf = 0; nf < 4; nf++)
                    mma16816(acc[mi][nf], a[mi],
                             bf[nf >> 1][(nf & 1) * 2], bf[nf >> 1][(nf & 1) * 2 + 1]);
        }
        __syncthreads();
        if (c + 2 < NCHUNK) load_chunk(c + 2);
    }

    // Epilogue: rowsum of tanh(acc + decb) * w_attn
    // c-frag: c0,c1 -> row lane/4, cols 2*(lane%4)+{0,1}; c2,c3 -> row +8
    #pragma unroll
    for (int mi = 0; mi < 4; mi++) {
        float sl = 0.f, sh = 0.f;
        #pragma unroll
        for (int nf = 0; nf < 4; nf++) {
            int cb = wn * 32 + nf * 8 + (lane & 3) * 2;
            sl += tanhf(acc[mi][nf][0] + s_db[cb])     * s_w[cb]
                + tanhf(acc[mi][nf][1] + s_db[cb + 1]) * s_w[cb + 1];
            sh += tanhf(acc[mi][nf][2] + s_db[cb])     * s_w[cb]
                + tanhf(acc[mi][nf][3] + s_db[cb + 1]) * s_w[cb + 1];
        }
        sl += __shfl_xor_sync(0xffffffffu, sl, 1);
        sl += __shfl_xor_sync(0xffffffffu, sl, 2);
        sh += __shfl_xor_sync(0xffffffffu, sh, 1);
        sh += __shfl_xor_sync(0xffffffffu, sh, 2);
        if ((lane & 3) == 0) {
            int r = wm * 64 + mi * 16 + (lane >> 2);
            rowsum[wn * BM + r]     = sl;
            rowsum[wn * BM + r + 8] = sh;
        }
    }
    __syncthreads();
    g_scores_part[blockIdx.x * Mn + m0 + tid] = rowsum[tid] + rowsum[BM + tid];
}

// ---------------------------------------------------------------------------
// Masked softmax per batch row; writes attn into d_out[32768 + b*2048 + s]
// ---------------------------------------------------------------------------
__global__ void softmax_kernel(const int* __restrict__ enc_len,
                               float* __restrict__ attn_out) {
    const int b = blockIdx.x;
    const int tid = threadIdx.x;
    __shared__ float red[256];
    __shared__ float sc[Sn];

    const int len = enc_len[b];

    float lmax = -INFINITY;
    for (int s = tid; s < Sn; s += 256) {
        float v = 0.f;
        #pragma unroll
        for (int ct = 0; ct < NTILES; ct++)
            v += g_scores_part[ct * Mn + b * Sn + s];
        sc[s] = v;
        if (s < len) lmax = fmaxf(lmax, v);
    }
    red[tid] = lmax;
    __syncthreads();
    for (int off = 128; off > 0; off >>= 1) {
        if (tid < off) red[tid] = fmaxf(red[tid], red[tid + off]);
        __syncthreads();
    }
    const float m = red[0];
    __syncthreads();

    float lsum = 0.f;
    for (int s = tid; s < Sn; s += 256) {
        float e = (s < len) ? expf(sc[s] - m) : 0.f;
        sc[s] = e;
        lsum += e;
    }
    red[tid] = lsum;
    __syncthreads();
    for (int off = 128; off > 0; off >>= 1) {
        if (tid < off) red[tid] += red[tid + off];
        __syncthreads();
    }
    const float inv = 1.f / red[0];
    __syncthreads();

    for (int s = tid; s < Sn; s += 256)
        attn_out[b * Sn + s] = sc[s] * inv;
}

// ---------------------------------------------------------------------------
// Context partials (fp32 enc_states for accuracy; near DRAM roofline already)
// ---------------------------------------------------------------------------
__global__ void context_kernel(const float* __restrict__ enc,
                               const float* __restrict__ attn) {
    const int ch = blockIdx.x;
    const int b = blockIdx.y;
    const int tid = threadIdx.x;
    const int d = tid * 4;
    __shared__ float wsh[128];
    if (tid < 128) wsh[tid] = attn[b * Sn + ch * 128 + tid];
    __syncthreads();

    float4 acc = make_float4(0.f, 0.f, 0.f, 0.f);
    const int s0 = ch * 128;
    for (int i = 0; i < 128; i++) {
        float w = wsh[i];
        float4 e = *reinterpret_cast<const float4*>(
            &enc[((size_t)b * Sn + s0 + i) * Dn + d]);
        acc.x = fmaf(w, e.x, acc.x);
        acc.y = fmaf(w, e.y, acc.y);
        acc.z = fmaf(w, e.z, acc.z);
        acc.w = fmaf(w, e.w, acc.w);
    }
    *reinterpret_cast<float4*>(&g_ctx_part[((size_t)ch * Bn + b) * Dn + d]) = acc;
}

// ---------------------------------------------------------------------------
// Output GEMM
// ---------------------------------------------------------------------------
__global__ void out_kernel(const float* __restrict__ Wout,
                           const float* __restrict__ bout,
                           float* __restrict__ out) {
    const int b = blockIdx.x;
    const int c = blockIdx.y * 256 + threadIdx.x;
    __shared__ float ctx[Dn];
    for (int k = threadIdx.x; k < Dn; k += 256) {
        float v = 0.f;
        #pragma unroll
        for (int ch = 0; ch < 16; ch++)
            v += g_ctx_part[((size_t)ch * Bn + b) * Dn + k];
        ctx[k] = v;
    }
    __syncthreads();
    float acc = bout[c];
    #pragma unroll 8
    for (int k = 0; k < Dn; k++)
        acc = fmaf(ctx[k], Wout[(size_t)k * Dn + c], acc);
    out[b * Dn + c] = acc;
}

// ---------------------------------------------------------------------------
// Launch
// ---------------------------------------------------------------------------
extern "C" void kernel_launch(void* const* d_in, const int* in_sizes, int n_in,
                              void* d_out, int out_size) {
    const float* enc   = (const float*)d_in[0];
    const float* dec   = (const float*)d_in[1];
    const float* Wenc  = (const float*)d_in[2];
    const float* benc  = (const float*)d_in[3];
    const float* Wdec  = (const float*)d_in[4];
    const float* bdec  = (const float*)d_in[5];
    const float* wattn = (const float*)d_in[6];
    const float* Wout  = (const float*)d_in[7];
    const float* bout  = (const float*)d_in[8];
    const int*   elen  = (const int*)d_in[9];

    float* out      = (float*)d_out;       // context [32*1024]
    float* attn_out = out + Bn * Dn;       // attn    [32*2048]

    cudaFuncSetAttribute(score_gemm_hmma,
                         cudaFuncAttributeMaxDynamicSharedMemorySize, SMEM_BYTES);

    convert_enc<<<(Mn * (Dn / 4)) / 256, 256>>>(enc);
    convert_W<<<Dn, Dn>>>(Wenc);
    dech_kernel<<<dim3(Bn, 4), 256>>>(dec, Wdec, bdec, benc);
    score_gemm_hmma<<<dim3(NTILES, Mn / BM), 256, SMEM_BYTES>>>(wattn);
    softmax_kernel<<<Bn, 256>>>(elen, attn_out);
    context_kernel<<<dim3(16, Bn), 256>>>(enc, attn_out);
    out_kernel<<<dim3(Bn, 4), 256>>>(Wout, bout, out);
}

// round 13
// speedup vs baseline: 7.1718x; 1.0354x over previous
#include <cuda_runtime.h>
#include <cuda_fp16.h>
#include <cstdint>
#include <math.h>

// Problem constants
#define Bn   32
#define Sn   2048
#define Dn   1024
#define Mn   (Bn * Sn)

// Score-GEMM tiling (mma.sync HMMA path — tcgen05 PTX is rejected by the
// harness's compute_103 PTX stage, so we use the arch-portable tensor path)
#define BM 128              // CTA rows  (8 warps: 4M x 2N, warp tile 32x64)
#define BN 128              // CTA cols  (was 64: halves A-tile L2 passes)
#define BK 64               // K per chunk
#define NTILES (Dn / BN)    // 8 column tiles
#define NCHUNK (Dn / BK)    // 16 chunks
#define NSTG 3              // 3-stage ring -> single barrier per chunk

#define ROWP 72             // SMEM row stride in halves (144 B = 36 banks ≡ 4
                            // mod 32 -> ldmatrix phases conflict-free)

// ---------------------------------------------------------------------------
// Scratch (static device globals; no allocation allowed)
// ---------------------------------------------------------------------------
__device__ float g_decb[Bn * Dn];                    // dec_h + b_dec + b_enc
__device__ float g_scores_part[NTILES * Mn];         // per-col-tile score partials
__device__ float g_ctx_part[16 * Bn * Dn];           // context partials
__device__ __half g_ench[(size_t)Mn * Dn];           // enc_states fp16 (128 MB)
__device__ __half g_WT[Dn * Dn];                     // W_enc^T fp16 (K-major: [n][k])

// ---------------------------------------------------------------------------
// PTX helpers (sm_80-compatible only: cp.async, ldmatrix, mma.sync)
// ---------------------------------------------------------------------------
__device__ __forceinline__ uint32_t smem_u32(const void* p) {
    uint32_t a;
    asm("{ .reg .u64 t; cvta.to.shared.u64 t, %1; cvt.u32.u64 %0, t; }" : "=r"(a) : "l"(p));
    return a;
}
__device__ __forceinline__ void cp_async16(uint32_t dst, const void* src) {
    asm volatile("cp.async.cg.shared.global [%0], [%1], 16;" :: "r"(dst), "l"(src));
}
__device__ __forceinline__ void cp_commit() {
    asm volatile("cp.async.commit_group;" ::: "memory");
}
template <int N>
__device__ __forceinline__ void cp_wait() {
    asm volatile("cp.async.wait_group %0;" :: "n"(N) : "memory");
}
__device__ __forceinline__ void ldsm4(uint32_t* r, uint32_t addr) {
    asm volatile("ldmatrix.sync.aligned.m8n8.x4.shared.b16 {%0,%1,%2,%3}, [%4];"
                 : "=r"(r[0]), "=r"(r[1]), "=r"(r[2]), "=r"(r[3]) : "r"(addr));
}
__device__ __forceinline__ void mma16816(float* c, const uint32_t* a,
                                         uint32_t b0, uint32_t b1) {
    asm volatile("mma.sync.aligned.m16n8k16.row.col.f32.f16.f16.f32 "
                 "{%0,%1,%2,%3}, {%4,%5,%6,%7}, {%8,%9}, {%0,%1,%2,%3};"
                 : "+f"(c[0]), "+f"(c[1]), "+f"(c[2]), "+f"(c[3])
                 : "r"(a[0]), "r"(a[1]), "r"(a[2]), "r"(a[3]), "r"(b0), "r"(b1));
}

// ---------------------------------------------------------------------------
// Pre-pass A: enc_states fp32 -> fp16 (RN)
// ---------------------------------------------------------------------------
__global__ void convert_enc(const float* __restrict__ enc) {
    size_t i = (size_t)blockIdx.x * blockDim.x + threadIdx.x;  // one float4 each
    float4 v = reinterpret_cast<const float4*>(enc)[i];
    __half2 p0 = __floats2half2_rn(v.x, v.y);
    __half2 p1 = __floats2half2_rn(v.z, v.w);
    uint2 u;
    u.x = *reinterpret_cast<uint32_t*>(&p0);
    u.y = *reinterpret_cast<uint32_t*>(&p1);
    reinterpret_cast<uint2*>(g_ench)[i] = u;
}

// ---------------------------------------------------------------------------
// Pre-pass B: W_enc [K,N] fp32 -> transposed K-major fp16
// ---------------------------------------------------------------------------
__global__ void convert_W(const float* __restrict__ W) {
    int n = blockIdx.x;
    int k = threadIdx.x;
    g_WT[(size_t)n * Dn + k] = __float2half_rn(W[(size_t)k * Dn + n]);
}

// ---------------------------------------------------------------------------
// decb[b,c] = b_dec[c] + b_enc[c] + dec_states[b,:] @ W_dec[:,c]
// ---------------------------------------------------------------------------
__global__ void dech_kernel(const float* __restrict__ dec,
                            const float* __restrict__ Wdec,
                            const float* __restrict__ bdec,
                            const float* __restrict__ benc) {
    const int b   = blockIdx.x;
    const int c   = blockIdx.y * 256 + threadIdx.x;
    __shared__ float dsh[Dn];
    for (int k = threadIdx.x; k < Dn; k += 256) dsh[k] = dec[b * Dn + k];
    __syncthreads();
    float acc = bdec[c] + benc[c];
    #pragma unroll 8
    for (int k = 0; k < Dn; k++)
        acc = fmaf(dsh[k], Wdec[(size_t)k * Dn + c], acc);
    g_decb[b * Dn + c] = acc;
}

// ---------------------------------------------------------------------------
// HMMA fused score GEMM (fp16, BK=64, 3-stage ring, ONE barrier per chunk).
//  D[128,128] = A_fp16[128,K] @ B_fp16[128,K]^T  (fp32 accum)
//  epilogue: rowsum of tanh(D + decb) * w_attn -> g_scores_part[tile_n][row]
//  8 warps, 4(M) x 2(N); warp tile 32x64; 16-MMA independence batches.
//  Ring invariant: at iter c, stage (c+2)%3 was last READ at iter c-1, which
//  all warps finished before this iter's barrier -> loads for chunk c+2 issue
//  right after the barrier and overlap the whole compute phase. No second
//  barrier (R12 had 2/chunk).
// ---------------------------------------------------------------------------
struct Stage {
    __half A[BM][ROWP];    // 18432 B
    __half B[BN][ROWP];    // 18432 B
};
#define B_OFF  (BM * ROWP * 2)             // byte offset of B within a stage
#define SMEM_BYTES (NSTG * (int)sizeof(Stage) + (BN + BN + 2 * BM) * 4)

__global__ __launch_bounds__(256)
void score_gemm_hmma(const float* __restrict__ wattn) {
    extern __shared__ char dsm[];
    float* s_db   = reinterpret_cast<float*>(dsm + NSTG * sizeof(Stage));
    float* s_w    = s_db + BN;
    float* rowsum = s_w + BN;                 // [2][BM]

    const int tid  = threadIdx.x;
    const int wid  = tid >> 5;
    const int lane = tid & 31;
    const int wm   = wid >> 1;     // 0..3 : 32-row group
    const int wn   = wid & 1;      // 0..1 : 64-col group
    const int n0   = blockIdx.x * BN;   // x = col tile -> CTAs share A in L2
    const int m0   = blockIdx.y * BM;
    const int b    = m0 >> 11;

    if (tid < BN) {
        s_db[tid] = g_decb[b * Dn + n0 + tid];
        s_w[tid]  = wattn[n0 + tid];
    }

    float acc[2][8][4];            // [mi][nf][frag] : 64 regs
    #pragma unroll
    for (int i = 0; i < 2; i++)
        #pragma unroll
        for (int j = 0; j < 8; j++)
            #pragma unroll
            for (int q = 0; q < 4; q++) acc[i][j][q] = 0.f;

    // ---- hoisted loader addressing ----
    const int s8 = (tid & 7) * 8;             // half offset within 64-half row
    const int r0 = tid >> 3;                  // 0..31
    const __half* aSrc = g_ench + ((size_t)m0 + r0) * Dn + s8;
    const __half* bSrc = g_WT + (size_t)(n0 + r0) * Dn + s8;
    uint32_t stgAddr[NSTG];
    #pragma unroll
    for (int s = 0; s < NSTG; s++) stgAddr[s] = smem_u32(dsm + s * sizeof(Stage));
    const uint32_t aDst = r0 * (ROWP * 2) + s8 * 2;           // within stage
    const uint32_t bDst = B_OFF + r0 * (ROWP * 2) + s8 * 2;

    auto load_chunk = [&](int c) {
        const uint32_t base = stgAddr[c % NSTG];
        const int k0 = c * BK;
        #pragma unroll
        for (int i = 0; i < 4; i++)           // A: 4 x 32 rows
            cp_async16(base + aDst + i * (32 * ROWP * 2),
                       aSrc + k0 + (size_t)i * 32 * Dn);
        #pragma unroll
        for (int i = 0; i < 4; i++)           // B: 4 x 32 rows
            cp_async16(base + bDst + i * (32 * ROWP * 2),
                       bSrc + k0 + (size_t)i * 32 * Dn);
        cp_commit();
    };

    // ---- hoisted ldmatrix addressing ----
    const uint32_t aLd = (wm * 32 + (lane & 15)) * (ROWP * 2) + (lane >> 4) * 16;
    const int quad = lane >> 3;
    const uint32_t bLd = B_OFF
        + (wn * 64 + ((quad & 2) ? 8 : 0) + (lane & 7)) * (ROWP * 2)
        + ((quad & 1) ? 16 : 0);

    load_chunk(0);
    load_chunk(1);

    for (int c = 0; c < NCHUNK; c++) {
        cp_wait<1>();                 // chunk c landed (c+1 may stay in flight)
        __syncthreads();              // all warps see it; stage (c+2)%3 is free
        if (c + 2 < NCHUNK) load_chunk(c + 2);   // overlaps compute below
        const uint32_t base = stgAddr[c % NSTG];

        #pragma unroll
        for (int kk = 0; kk < 4; kk++) {              // four k16 steps per chunk
            const uint32_t kboff = kk * 32;           // kb*2 bytes
            uint32_t a[2][4];
            #pragma unroll
            for (int mi = 0; mi < 2; mi++)
                ldsm4(a[mi], base + aLd + mi * (16 * ROWP * 2) + kboff);
            uint32_t bf[4][4];
            #pragma unroll
            for (int p = 0; p < 4; p++)
                ldsm4(bf[p], base + bLd + p * (16 * ROWP * 2) + kboff);
            // 16 independent MMAs (16 distinct accumulators)
            #pragma unroll
            for (int mi = 0; mi < 2; mi++)
                #pragma unroll
                for (int nf = 0; nf < 8; nf++)
                    mma16816(acc[mi][nf], a[mi],
                             bf[nf >> 1][(nf & 1) * 2], bf[nf >> 1][(nf & 1) * 2 + 1]);
        }
    }

    // Epilogue: rowsum of tanh(acc + decb) * w_attn
    // c-frag: c0,c1 -> row lane/4, cols 2*(lane%4)+{0,1}; c2,c3 -> row +8
    __syncthreads();                  // loads done; reuse of rowsum region safe
    #pragma unroll
    for (int mi = 0; mi < 2; mi++) {
        float sl = 0.f, sh = 0.f;
        #pragma unroll
        for (int nf = 0; nf < 8; nf++) {
            int cb = wn * 64 + nf * 8 + (lane & 3) * 2;
            sl += tanhf(acc[mi][nf][0] + s_db[cb])     * s_w[cb]
                + tanhf(acc[mi][nf][1] + s_db[cb + 1]) * s_w[cb + 1];
            sh += tanhf(acc[mi][nf][2] + s_db[cb])     * s_w[cb]
                + tanhf(acc[mi][nf][3] + s_db[cb + 1]) * s_w[cb + 1];
        }
        sl += __shfl_xor_sync(0xffffffffu, sl, 1);
        sl += __shfl_xor_sync(0xffffffffu, sl, 2);
        sh += __shfl_xor_sync(0xffffffffu, sh, 1);
        sh += __shfl_xor_sync(0xffffffffu, sh, 2);
        if ((lane & 3) == 0) {
            int r = wm * 32 + mi * 16 + (lane >> 2);
            rowsum[wn * BM + r]     = sl;
            rowsum[wn * BM + r + 8] = sh;
        }
    }
    __syncthreads();
    if (tid < BM)
        g_scores_part[blockIdx.x * Mn + m0 + tid] = rowsum[tid] + rowsum[BM + tid];
}

// ---------------------------------------------------------------------------
// Masked softmax per batch row; writes attn into d_out[32768 + b*2048 + s]
// ---------------------------------------------------------------------------
__global__ void softmax_kernel(const int* __restrict__ enc_len,
                               float* __restrict__ attn_out) {
    const int b = blockIdx.x;
    const int tid = threadIdx.x;
    __shared__ float red[256];
    __shared__ float sc[Sn];

    const int len = enc_len[b];

    float lmax = -INFINITY;
    for (int s = tid; s < Sn; s += 256) {
        float v = 0.f;
        #pragma unroll
        for (int ct = 0; ct < NTILES; ct++)
            v += g_scores_part[ct * Mn + b * Sn + s];
        sc[s] = v;
        if (s < len) lmax = fmaxf(lmax, v);
    }
    red[tid] = lmax;
    __syncthreads();
    for (int off = 128; off > 0; off >>= 1) {
        if (tid < off) red[tid] = fmaxf(red[tid], red[tid + off]);
        __syncthreads();
    }
    const float m = red[0];
    __syncthreads();

    float lsum = 0.f;
    for (int s = tid; s < Sn; s += 256) {
        float e = (s < len) ? expf(sc[s] - m) : 0.f;
        sc[s] = e;
        lsum += e;
    }
    red[tid] = lsum;
    __syncthreads();
    for (int off = 128; off > 0; off >>= 1) {
        if (tid < off) red[tid] += red[tid + off];
        __syncthreads();
    }
    const float inv = 1.f / red[0];
    __syncthreads();

    for (int s = tid; s < Sn; s += 256)
        attn_out[b * Sn + s] = sc[s] * inv;
}

// ---------------------------------------------------------------------------
// Context partials (fp32 enc_states for accuracy; near DRAM roofline already)
// ---------------------------------------------------------------------------
__global__ void context_kernel(const float* __restrict__ enc,
                               const float* __restrict__ attn) {
    const int ch = blockIdx.x;
    const int b = blockIdx.y;
    const int tid = threadIdx.x;
    const int d = tid * 4;
    __shared__ float wsh[128];
    if (tid < 128) wsh[tid] = attn[b * Sn + ch * 128 + tid];
    __syncthreads();

    float4 acc = make_float4(0.f, 0.f, 0.f, 0.f);
    const int s0 = ch * 128;
    for (int i = 0; i < 128; i++) {
        float w = wsh[i];
        float4 e = *reinterpret_cast<const float4*>(
            &enc[((size_t)b * Sn + s0 + i) * Dn + d]);
        acc.x = fmaf(w, e.x, acc.x);
        acc.y = fmaf(w, e.y, acc.y);
        acc.z = fmaf(w, e.z, acc.z);
        acc.w = fmaf(w, e.w, acc.w);
    }
    *reinterpret_cast<float4*>(&g_ctx_part[((size_t)ch * Bn + b) * Dn + d]) = acc;
}

// ---------------------------------------------------------------------------
// Output GEMM
// ---------------------------------------------------------------------------
__global__ void out_kernel(const float* __restrict__ Wout,
                           const float* __restrict__ bout,
                           float* __restrict__ out) {
    const int b = blockIdx.x;
    const int c = blockIdx.y * 256 + threadIdx.x;
    __shared__ float ctx[Dn];
    for (int k = threadIdx.x; k < Dn; k += 256) {
        float v = 0.f;
        #pragma unroll
        for (int ch = 0; ch < 16; ch++)
            v += g_ctx_part[((size_t)ch * Bn + b) * Dn + k];
        ctx[k] = v;
    }
    __syncthreads();
    float acc = bout[c];
    #pragma unroll 8
    for (int k = 0; k < Dn; k++)
        acc = fmaf(ctx[k], Wout[(size_t)k * Dn + c], acc);
    out[b * Dn + c] = acc;
}

// ---------------------------------------------------------------------------
// Launch
// ---------------------------------------------------------------------------
extern "C" void kernel_launch(void* const* d_in, const int* in_sizes, int n_in,
                              void* d_out, int out_size) {
    const float* enc   = (const float*)d_in[0];
    const float* dec   = (const float*)d_in[1];
    const float* Wenc  = (const float*)d_in[2];
    const float* benc  = (const float*)d_in[3];
    const float* Wdec  = (const float*)d_in[4];
    const float* bdec  = (const float*)d_in[5];
    const float* wattn = (const float*)d_in[6];
    const float* Wout  = (const float*)d_in[7];
    const float* bout  = (const float*)d_in[8];
    const int*   elen  = (const int*)d_in[9];

    float* out      = (float*)d_out;       // context [32*1024]
    float* attn_out = out + Bn * Dn;       // attn    [32*2048]

    cudaFuncSetAttribute(score_gemm_hmma,
                         cudaFuncAttributeMaxDynamicSharedMemorySize, SMEM_BYTES);

    convert_enc<<<(Mn * (Dn / 4)) / 256, 256>>>(enc);
    convert_W<<<Dn, Dn>>>(Wenc);
    dech_kernel<<<dim3(Bn, 4), 256>>>(dec, Wdec, bdec, benc);
    score_gemm_hmma<<<dim3(NTILES, Mn / BM), 256, SMEM_BYTES>>>(wattn);
    softmax_kernel<<<Bn, 256>>>(elen, attn_out);
    context_kernel<<<dim3(16, Bn), 256>>>(enc, attn_out);
    out_kernel<<<dim3(Bn, 4), 256>>>(Wout, bout, out);
}